// round 5
// baseline (speedup 1.0000x reference)
#include <cuda_runtime.h>
#include <cuda_fp16.h>
#include <cstdint>

// CrossAttUnit fused — fp16-split (Ootomo) mma.sync, software-pipelined version.
// N=262144, H=256, D=64, L=64, B=4096. 1 segment/CTA, 256 threads, 3 CTAs/SM.
// Streaming: K=256 in 8 chunks of 32; A prefetched via regs, B via cp.async
// (double-buffered). 32-wide tiles use XOR swizzle (granule ^= (row>>1)&3).

#define HDIM 256
#define PITCH 72            // pitch for GEMM2 64-wide tiles (conflict-free LDSM)
#define FPITCH 68

// half-index offsets in dynamic smem (32768 halfs = 65536 B)
#define STA(s)   ((s) * 8192u)              // A stage: yhi,ylo,hhi,hlo @ +0,+2048,+4096,+6144
#define STB(s)   (16384u + (s) * 8192u)     // B stage: Khi,Klo,Qhi,Qlo
#define YKHI 0u
#define YKLO 4608u
#define YQHI 9216u
#define YQLO 13824u
#define ATTN_H 20480u                       // fp32 logits [64][68] = 8704 halfs
#define SMEM_BYTES 65536u

// pre-packed B: 8 chunks x 4 bufs x 2048 halfs, exact swizzled smem image
__device__ __align__(16) __half g_b[65536];

__global__ void split_kq_kernel(const float* __restrict__ kmat,
                                const float* __restrict__ qmat) {
    int gid = blockIdx.x * 256 + threadIdx.x;    // 32768 = 2 mats x 256 k x 64 n
    int mat = gid >> 14, k = (gid >> 6) & 255, n = gid & 63;
    float x = mat ? qmat[k * 64 + n] : kmat[k * 64 + n];
    __half hi = __float2half_rn(x);
    __half lo = __float2half_rn(x - __half2float(hi));
    int c = k >> 5, kw = k & 31;
    uint32_t off = (uint32_t)(n * 32 + ((((kw >> 3) ^ ((n >> 1) & 3))) << 3) + (kw & 7));
    g_b[(uint32_t)(c * 4 + mat * 2)     * 2048u + off] = hi;
    g_b[(uint32_t)(c * 4 + mat * 2 + 1) * 2048u + off] = lo;
}

__device__ __forceinline__ uint32_t smem_u32(const void* p) {
    uint32_t a;
    asm("{ .reg .u64 t; cvta.to.shared.u64 t, %1; cvt.u32.u64 %0, t; }" : "=r"(a) : "l"(p));
    return a;
}
__device__ __forceinline__ void ldsm4(uint32_t r[4], uint32_t addr) {
    asm volatile("ldmatrix.sync.aligned.m8n8.x4.shared.b16 {%0,%1,%2,%3}, [%4];"
                 : "=r"(r[0]), "=r"(r[1]), "=r"(r[2]), "=r"(r[3]) : "r"(addr));
}
__device__ __forceinline__ void mma16816(float c[4], const uint32_t a[4],
                                         uint32_t b0, uint32_t b1) {
    asm volatile(
        "mma.sync.aligned.m16n8k16.row.col.f32.f16.f16.f32 "
        "{%0,%1,%2,%3},{%4,%5,%6,%7},{%8,%9},{%0,%1,%2,%3};"
        : "+f"(c[0]), "+f"(c[1]), "+f"(c[2]), "+f"(c[3])
        : "r"(a[0]), "r"(a[1]), "r"(a[2]), "r"(a[3]), "r"(b0), "r"(b1));
}
__device__ __forceinline__ void split2(float x0, float x1, uint32_t& hi, uint32_t& lo) {
    __half h0 = __float2half_rn(x0), h1 = __float2half_rn(x1);
    __half l0 = __float2half_rn(x0 - __half2float(h0));
    __half l1 = __float2half_rn(x1 - __half2float(h1));
    __half2 H = __halves2half2(h0, h1), L = __halves2half2(l0, l1);
    hi = *(uint32_t*)&H;
    lo = *(uint32_t*)&L;
}
// swizzled 32-wide tile fragment address (tile: [row][32 halfs], granule perm)
__device__ __forceinline__ uint32_t laddr(uint32_t sb, uint32_t tile, int r0, int ks, int lane) {
    int row = r0 + (lane & 15);
    int kg = ks * 2 + (lane >> 4);
    return sb + (tile + (uint32_t)(row * 32 + ((kg ^ ((row >> 1) & 3)) << 3))) * 2u;
}
// plain pitch-72 fragment address (GEMM2 tiles)
__device__ __forceinline__ uint32_t addr72(uint32_t sb, uint32_t tile, int lane) {
    int row = lane & 15, colh = (lane >> 4) << 3;
    return sb + (tile + (uint32_t)(row * PITCH + colh)) * 2u;
}

#define CP_ASYNC16(saddr, gptr) \
    asm volatile("cp.async.cg.shared.global [%0], [%1], 16;" :: "r"(saddr), "l"(gptr) : "memory")
#define CP_COMMIT() asm volatile("cp.async.commit_group;" ::: "memory")
#define CP_WAIT0()  asm volatile("cp.async.wait_group 0;" ::: "memory")

__global__ __launch_bounds__(256, 3)
void cross_att_pipe(const float* __restrict__ yhat,
                    const float* __restrict__ y,
                    float* __restrict__ out) {
    extern __shared__ __half smem[];
    const uint32_t sb = smem_u32(smem);
    const int tid = threadIdx.x, wid = tid >> 5, lane = tid & 31;
    __shared__ float part[4][64];
    __shared__ float csum_inv[64];

    const long rowbase = (long)blockIdx.x * 64;
    const int mat = wid >> 2;                 // 0: yk ; 1: yq
    const int w2 = wid & 3;
    const int mrow0 = (w2 & 1) * 32;          // warp's 32-row block
    const int ncol0 = (w2 >> 1) * 32;         // warp's 32-col block

    float cc[2][4][4];
    #pragma unroll
    for (int a = 0; a < 2; a++)
        #pragma unroll
        for (int b = 0; b < 4; b++)
            #pragma unroll
            for (int j = 0; j < 4; j++) cc[a][b][j] = 0.0f;

    // ---- prologue: cp.async B chunk0 -> stage0 ; LDG A chunk0 -> regs ----
    {
        const char* src = (const char*)g_b;
        #pragma unroll
        for (int i = 0; i < 4; i++) {
            const uint32_t idx = (uint32_t)(i * 256 + tid);
            CP_ASYNC16(sb + 32768u + idx * 16u, src + idx * 16);
        }
        CP_COMMIT();
    }
    const int ar = tid >> 2, ag = tid & 3;
    const float* yp = y    + (rowbase + ar) * HDIM + ag * 8;
    const float* hp = yhat + (rowbase + ar) * HDIM + ag * 8;
    const uint32_t asw = (uint32_t)(ar * 32 + ((ag ^ ((ar >> 1) & 3)) << 3));
    float4 py0 = *(const float4*)yp,       py1 = *(const float4*)(yp + 4);
    float4 ph0 = *(const float4*)hp,       ph1 = *(const float4*)(hp + 4);

    // ---------------- pipelined GEMM1 over 8 chunks of K=32 ----------------
    #pragma unroll 1
    for (int c = 0; c < 8; c++) {
        const uint32_t sa = STA(c & 1);
        {   // split A regs -> 4 x STS.128
            uint32_t h0, h1, h2, h3, l0, l1, l2, l3;
            split2(py0.x, py0.y, h0, l0); split2(py0.z, py0.w, h1, l1);
            split2(py1.x, py1.y, h2, l2); split2(py1.z, py1.w, h3, l3);
            *(uint4*)&smem[sa + 0u    + asw] = make_uint4(h0, h1, h2, h3);
            *(uint4*)&smem[sa + 2048u + asw] = make_uint4(l0, l1, l2, l3);
            split2(ph0.x, ph0.y, h0, l0); split2(ph0.z, ph0.w, h1, l1);
            split2(ph1.x, ph1.y, h2, l2); split2(ph1.z, ph1.w, h3, l3);
            *(uint4*)&smem[sa + 4096u + asw] = make_uint4(h0, h1, h2, h3);
            *(uint4*)&smem[sa + 6144u + asw] = make_uint4(l0, l1, l2, l3);
        }
        if (c < 7) {   // A prefetch for next chunk
            py0 = *(const float4*)(yp + (c + 1) * 32);
            py1 = *(const float4*)(yp + (c + 1) * 32 + 4);
            ph0 = *(const float4*)(hp + (c + 1) * 32);
            ph1 = *(const float4*)(hp + (c + 1) * 32 + 4);
        }
        CP_WAIT0();
        __syncthreads();
        if (c < 7) {   // B prefetch for next chunk (other stage)
            const char* src = (const char*)g_b + (c + 1) * 16384;
            const uint32_t dst = sb + 32768u + (uint32_t)(((c + 1) & 1) * 16384);
            #pragma unroll
            for (int i = 0; i < 4; i++) {
                const uint32_t idx = (uint32_t)(i * 256 + tid);
                CP_ASYNC16(dst + idx * 16u, src + idx * 16);
            }
            CP_COMMIT();
        }
        // ---- MMA phase: warp tile 32x32, chunk K=32 (2 k16 steps) ----
        const uint32_t A_HI = sa + (mat ? 4096u : 0u), A_LO = A_HI + 2048u;
        const uint32_t B_HI = STB(c & 1) + (mat ? 4096u : 0u), B_LO = B_HI + 2048u;
        #pragma unroll
        for (int ks = 0; ks < 2; ks++) {
            uint32_t ah0[4], al0[4], ah1[4], al1[4];
            ldsm4(ah0, laddr(sb, A_HI, mrow0,      ks, lane));
            ldsm4(al0, laddr(sb, A_LO, mrow0,      ks, lane));
            ldsm4(ah1, laddr(sb, A_HI, mrow0 + 16, ks, lane));
            ldsm4(al1, laddr(sb, A_LO, mrow0 + 16, ks, lane));
            #pragma unroll
            for (int n16 = 0; n16 < 2; n16++) {
                uint32_t bh[4], bl[4];
                ldsm4(bh, laddr(sb, B_HI, ncol0 + n16 * 16, ks, lane));
                ldsm4(bl, laddr(sb, B_LO, ncol0 + n16 * 16, ks, lane));
                const int nb = n16 * 2;
                mma16816(cc[0][nb],     ah0, bh[0], bh[2]);
                mma16816(cc[0][nb],     ah0, bl[0], bl[2]);
                mma16816(cc[0][nb],     al0, bh[0], bh[2]);
                mma16816(cc[0][nb + 1], ah0, bh[1], bh[3]);
                mma16816(cc[0][nb + 1], ah0, bl[1], bl[3]);
                mma16816(cc[0][nb + 1], al0, bh[1], bh[3]);
                mma16816(cc[1][nb],     ah1, bh[0], bh[2]);
                mma16816(cc[1][nb],     ah1, bl[0], bl[2]);
                mma16816(cc[1][nb],     al1, bh[0], bh[2]);
                mma16816(cc[1][nb + 1], ah1, bh[1], bh[3]);
                mma16816(cc[1][nb + 1], ah1, bl[1], bl[3]);
                mma16816(cc[1][nb + 1], al1, bh[1], bh[3]);
            }
        }
    }
    __syncthreads();   // all stage reads done; tile region reusable

    // ---------------- split yk/yq accumulators -> GEMM2 tiles [64][72] ----------------
    {
        const uint32_t HIb = mat ? YQHI : YKHI, LOb = HIb + 4608u;
        const int r0 = mrow0 + (lane >> 2), cb = (lane & 3) * 2;
        #pragma unroll
        for (int mt = 0; mt < 2; mt++)
            #pragma unroll
            for (int n8 = 0; n8 < 4; n8++) {
                const int rr = r0 + mt * 16;
                const int col = ncol0 + n8 * 8 + cb;
                uint32_t hi, lo;
                split2(cc[mt][n8][0], cc[mt][n8][1], hi, lo);
                *(uint32_t*)&smem[HIb + (uint32_t)(rr * PITCH + col)] = hi;
                *(uint32_t*)&smem[LOb + (uint32_t)(rr * PITCH + col)] = lo;
                split2(cc[mt][n8][2], cc[mt][n8][3], hi, lo);
                *(uint32_t*)&smem[HIb + (uint32_t)((rr + 8) * PITCH + col)] = hi;
                *(uint32_t*)&smem[LOb + (uint32_t)((rr + 8) * PITCH + col)] = lo;
            }
    }
    __syncthreads();

    // ---------------- GEMM2: M = yk @ yq^T ; warp = (rt rows, ch col-half) ----------------
    float* attnf = (float*)&smem[ATTN_H];        // [64][68] fp32, disjoint region
    {
        const int rt = wid & 3, ch = wid >> 2;
        const int ct = ch * 32;
        float cm[4][4];
        #pragma unroll
        for (int n = 0; n < 4; n++)
            #pragma unroll
            for (int j = 0; j < 4; j++) cm[n][j] = 0.0f;

        #pragma unroll
        for (int ks = 0; ks < 4; ks++) {
            uint32_t Ah[4], Al[4];
            const uint32_t at = (uint32_t)(rt * 16 * PITCH + ks * 16);
            ldsm4(Ah, addr72(sb, YKHI + at, lane));
            ldsm4(Al, addr72(sb, YKLO + at, lane));
            #pragma unroll
            for (int nl = 0; nl < 2; nl++) {
                const uint32_t bt = (uint32_t)((ct + nl * 16) * PITCH + ks * 16);
                uint32_t Bh[4], Bl[4];
                ldsm4(Bh, addr72(sb, YQHI + bt, lane));
                ldsm4(Bl, addr72(sb, YQLO + bt, lane));
                mma16816(cm[2 * nl],     Ah, Bh[0], Bh[2]);
                mma16816(cm[2 * nl],     Ah, Bl[0], Bl[2]);
                mma16816(cm[2 * nl],     Al, Bh[0], Bh[2]);
                mma16816(cm[2 * nl + 1], Ah, Bh[1], Bh[3]);
                mma16816(cm[2 * nl + 1], Ah, Bl[1], Bl[3]);
                mma16816(cm[2 * nl + 1], Al, Bh[1], Bh[3]);
            }
        }
        // write scaled logits (disjoint region -> no sync needed first)
        const int r0 = rt * 16 + (lane >> 2);
        const int cb = (lane & 3) * 2;
        #pragma unroll
        for (int nt = 0; nt < 4; nt++) {
            const int colb = ct + nt * 8 + cb;
            *(float2*)&attnf[r0 * FPITCH + colb] =
                make_float2(cm[nt][0] * 0.125f, cm[nt][1] * 0.125f);
            *(float2*)&attnf[(r0 + 8) * FPITCH + colb] =
                make_float2(cm[nt][2] * 0.125f, cm[nt][3] * 0.125f);
        }
    }
    __syncthreads();

    // ---------------- row softmax + EPS ----------------
    #pragma unroll 1
    for (int rr = 0; rr < 8; rr++) {
        const int r = wid * 8 + rr;
        float v0 = attnf[r * FPITCH + lane];
        float v1 = attnf[r * FPITCH + lane + 32];
        float mx = fmaxf(v0, v1);
        #pragma unroll
        for (int o = 16; o > 0; o >>= 1)
            mx = fmaxf(mx, __shfl_xor_sync(0xffffffffu, mx, o));
        float e0 = __expf(v0 - mx);
        float e1 = __expf(v1 - mx);
        float s = e0 + e1;
        #pragma unroll
        for (int o = 16; o > 0; o >>= 1)
            s += __shfl_xor_sync(0xffffffffu, s, o);
        const float inv = 1.0f / s;
        attnf[r * FPITCH + lane]      = e0 * inv + 1e-6f;
        attnf[r * FPITCH + lane + 32] = e1 * inv + 1e-6f;
    }
    __syncthreads();

    // ---------------- column sums + normalize + store ----------------
    {
        const int col = tid & 63, q = tid >> 6;
        float s = 0.0f;
        #pragma unroll
        for (int l = 0; l < 16; l++) s += attnf[(q * 16 + l) * FPITCH + col];
        part[q][col] = s;
    }
    __syncthreads();
    if (tid < 64)
        csum_inv[tid] = 1.0f / (part[0][tid] + part[1][tid] + part[2][tid] + part[3][tid]);
    __syncthreads();

    {
        float* outb = out + (long)blockIdx.x * 4096;
        #pragma unroll
        for (int e = 0; e < 4; e++) {
            const int f4 = e * 256 + tid;
            const int l = f4 >> 4, m0 = (f4 & 15) * 4;
            float4 v = *(const float4*)&attnf[l * FPITCH + m0];
            v.x *= csum_inv[m0 + 0];
            v.y *= csum_inv[m0 + 1];
            v.z *= csum_inv[m0 + 2];
            v.w *= csum_inv[m0 + 3];
            *(float4*)&outb[l * 64 + m0] = v;
        }
    }
}

extern "C" void kernel_launch(void* const* d_in, const int* in_sizes, int n_in,
                              void* d_out, int out_size) {
    const float* yhat = (const float*)d_in[0];
    const float* y    = (const float*)d_in[1];
    const float* kmat = (const float*)d_in[2];
    const float* qmat = (const float*)d_in[3];
    float* out = (float*)d_out;

    const int N = in_sizes[1] / HDIM;
    const int grid = N / 64;

    split_kq_kernel<<<128, 256>>>(kmat, qmat);

    cudaFuncSetAttribute(cross_att_pipe,
                         cudaFuncAttributeMaxDynamicSharedMemorySize, (int)SMEM_BYTES);
    cudaFuncSetAttribute(cross_att_pipe,
                         cudaFuncAttributePreferredSharedMemoryCarveout, 100);
    cross_att_pipe<<<grid, 256, SMEM_BYTES>>>(yhat, y, out);
}

// round 6
// speedup vs baseline: 1.0070x; 1.0070x over previous
#include <cuda_runtime.h>
#include <cuda_fp16.h>
#include <cstdint>

// CrossAttUnit fused — fp16-split (Ootomo) mma.sync, M=128 (2 segments/CTA).
// N=262144, H=256, D=64, L=64, B=4096. 2048 CTAs, 256 threads, 2 CTAs/SM.
// GEMM1 tiles: SW128-swizzled, pitch 64 halfs (128B rows). GEMM2 tiles: pitch 72.

#define HDIM 256
#define PITCH 72
#define FPITCH 68

// byte offsets in dynamic smem (98304 B total)
#define TB_YHI 0u
#define TB_YLO 16384u
#define TB_HHI 32768u
#define TB_HLO 49152u
#define TB_B   65536u          // 4 bufs x 8192 B: Khi,Klo,Qhi,Qlo
// GEMM2 tile half-indices (alias bytes 0..73728 after GEMM1)
#define YK2HI 0u
#define YK2LO 9216u
#define YQ2HI 18432u
#define YQ2LO 27648u
#define SMEM_BYTES 98304u

// pre-packed B image: [chunk 0..3][buf 0..3][4096 halfs, sw128 rows of 64]
__device__ __align__(16) __half g_b[65536];

__global__ void split_kq_kernel(const float* __restrict__ kmat,
                                const float* __restrict__ qmat) {
    int gid = blockIdx.x * 256 + threadIdx.x;    // 32768 = 2 x 256 x 64
    int mat = gid >> 14, k = (gid >> 6) & 255, n = gid & 63;
    float x = mat ? qmat[k * 64 + n] : kmat[k * 64 + n];
    __half hi = __float2half_rn(x);
    __half lo = __float2half_rn(x - __half2float(hi));
    int c = k >> 6, kk = k & 63;
    uint32_t off = (uint32_t)(kk * 64 + ((((n >> 3) ^ (kk & 7))) << 3) + (n & 7));
    g_b[(uint32_t)(c * 4 + mat * 2)     * 4096u + off] = hi;
    g_b[(uint32_t)(c * 4 + mat * 2 + 1) * 4096u + off] = lo;
}

__device__ __forceinline__ uint32_t smem_u32(const void* p) {
    uint32_t a;
    asm("{ .reg .u64 t; cvta.to.shared.u64 t, %1; cvt.u32.u64 %0, t; }" : "=r"(a) : "l"(p));
    return a;
}
__device__ __forceinline__ void ldsm4(uint32_t r[4], uint32_t addr) {
    asm volatile("ldmatrix.sync.aligned.m8n8.x4.shared.b16 {%0,%1,%2,%3}, [%4];"
                 : "=r"(r[0]), "=r"(r[1]), "=r"(r[2]), "=r"(r[3]) : "r"(addr));
}
__device__ __forceinline__ void ldsm4t(uint32_t r[4], uint32_t addr) {
    asm volatile("ldmatrix.sync.aligned.m8n8.x4.trans.shared.b16 {%0,%1,%2,%3}, [%4];"
                 : "=r"(r[0]), "=r"(r[1]), "=r"(r[2]), "=r"(r[3]) : "r"(addr));
}
__device__ __forceinline__ void mma16816(float c[4], const uint32_t a[4],
                                         uint32_t b0, uint32_t b1) {
    asm volatile(
        "mma.sync.aligned.m16n8k16.row.col.f32.f16.f16.f32 "
        "{%0,%1,%2,%3},{%4,%5,%6,%7},{%8,%9},{%0,%1,%2,%3};"
        : "+f"(c[0]), "+f"(c[1]), "+f"(c[2]), "+f"(c[3])
        : "r"(a[0]), "r"(a[1]), "r"(a[2]), "r"(a[3]), "r"(b0), "r"(b1));
}
__device__ __forceinline__ void split2(float x0, float x1, uint32_t& hi, uint32_t& lo) {
    __half h0 = __float2half_rn(x0), h1 = __float2half_rn(x1);
    __half l0 = __float2half_rn(x0 - __half2float(h0));
    __half l1 = __float2half_rn(x1 - __half2float(h1));
    __half2 H = __halves2half2(h0, h1), L = __halves2half2(l0, l1);
    hi = *(uint32_t*)&H;
    lo = *(uint32_t*)&L;
}
// ldsm A (non-trans) from sw128 pitch-64 tile: 16x16 at (r0, ks*16)
__device__ __forceinline__ uint32_t aAddr(uint32_t sb, uint32_t tb, int r0, int ks, int lane) {
    int row = r0 + (lane & 15);
    int g = ((lane >> 4) + ks * 2) ^ (row & 7);
    return sb + tb + (uint32_t)(row * 128 + (g << 4));
}
// ldsm B (trans) from sw128 pitch-64 tile [k][n]: 16(k)x16(n) at (ks*16, np*16)
__device__ __forceinline__ uint32_t bAddr(uint32_t sb, uint32_t tb, int np, int ks, int lane) {
    int q = lane >> 3, i = lane & 7;
    int k = ks * 16 + ((q & 1) << 3) + i;
    int g = (np * 2 + (q >> 1)) ^ i;
    return sb + tb + (uint32_t)(k * 128 + (g << 4));
}
// plain pitch-72 fragment address (GEMM2 tiles), tile half-offset
__device__ __forceinline__ uint32_t addr72(uint32_t sb, uint32_t tile, int lane) {
    int row = lane & 15, colh = (lane >> 4) << 3;
    return sb + (tile + (uint32_t)(row * PITCH + colh)) * 2u;
}

#define CP_ASYNC16(saddr, gptr) \
    asm volatile("cp.async.cg.shared.global [%0], [%1], 16;" :: "r"(saddr), "l"(gptr) : "memory")
#define CP_COMMIT() asm volatile("cp.async.commit_group;" ::: "memory")
#define CP_WAIT0()  asm volatile("cp.async.wait_group 0;" ::: "memory")

__global__ __launch_bounds__(256, 2)
void cross_att_m128(const float* __restrict__ yhat,
                    const float* __restrict__ y,
                    float* __restrict__ out) {
    extern __shared__ __half smem[];
    char* sc = (char*)smem;
    const uint32_t sb = smem_u32(smem);
    const int tid = threadIdx.x, wid = tid >> 5, lane = tid & 31;
    __shared__ float part[2][128];
    __shared__ float csum_inv[128];

    const long rowbase = (long)blockIdx.x * 128;
    const int mat = wid >> 2;                  // 0: yk (y,k) ; 1: yq (yhat,q)
    const int mrow0 = (wid & 3) * 32;          // warp's 32-row block within its mat

    float cc[2][8][4];
    #pragma unroll
    for (int a = 0; a < 2; a++)
        #pragma unroll
        for (int b = 0; b < 8; b++)
            #pragma unroll
            for (int j = 0; j < 4; j++) cc[a][b][j] = 0.0f;

    // ---------------- GEMM1: 4 chunks of K=64 ----------------
    #pragma unroll 1
    for (int c = 0; c < 4; c++) {
        // B tiles via cp.async (32 KB: 2048 x 16B)
        {
            const char* src = (const char*)g_b + c * 32768;
            #pragma unroll
            for (int i = 0; i < 8; i++) {
                const uint32_t idx = (uint32_t)(i * 256 + tid);
                CP_ASYNC16(sb + TB_B + idx * 16u, src + idx * 16);
            }
            CP_COMMIT();
        }
        // A: 128 rows x 64 cols, both mats, fp32 -> hi/lo fp16 (sw128 tiles)
        #pragma unroll
        for (int t = 0; t < 8; t++) {
            const int idx = tid + t * 256;          // 0..2047
            const int r = idx >> 4, k4 = idx & 15;
            const long g = (rowbase + r) * HDIM + c * 64 + k4 * 4;
            float4 vy = *(const float4*)&y[g];
            float4 vh = *(const float4*)&yhat[g];
            uint2 yh, yl, hh, hl;
            split2(vy.x, vy.y, yh.x, yl.x); split2(vy.z, vy.w, yh.y, yl.y);
            split2(vh.x, vh.y, hh.x, hl.x); split2(vh.z, vh.w, hh.y, hl.y);
            const uint32_t boff = (uint32_t)(r * 128 + ((((k4 >> 1) ^ (r & 7)) << 4) | ((k4 & 1) << 3)));
            *(uint2*)(sc + TB_YHI + boff) = yh;
            *(uint2*)(sc + TB_YLO + boff) = yl;
            *(uint2*)(sc + TB_HHI + boff) = hh;
            *(uint2*)(sc + TB_HLO + boff) = hl;
        }
        CP_WAIT0();
        __syncthreads();

        const uint32_t A_HI = mat ? TB_HHI : TB_YHI;
        const uint32_t A_LO = mat ? TB_HLO : TB_YLO;
        const uint32_t B_HI = TB_B + (mat ? 16384u : 0u);
        const uint32_t B_LO = B_HI + 8192u;

        #pragma unroll
        for (int ks = 0; ks < 4; ks++) {
            uint32_t ah0[4], al0[4], ah1[4], al1[4];
            ldsm4(ah0, aAddr(sb, A_HI, mrow0,      ks, lane));
            ldsm4(al0, aAddr(sb, A_LO, mrow0,      ks, lane));
            ldsm4(ah1, aAddr(sb, A_HI, mrow0 + 16, ks, lane));
            ldsm4(al1, aAddr(sb, A_LO, mrow0 + 16, ks, lane));
            #pragma unroll
            for (int np = 0; np < 4; np++) {
                uint32_t bh[4], bl[4];
                ldsm4t(bh, bAddr(sb, B_HI, np, ks, lane));
                ldsm4t(bl, bAddr(sb, B_LO, np, ks, lane));
                const int nb = np * 2;
                mma16816(cc[0][nb],     ah0, bh[0], bh[1]);
                mma16816(cc[0][nb],     ah0, bl[0], bl[1]);
                mma16816(cc[0][nb],     al0, bh[0], bh[1]);
                mma16816(cc[0][nb + 1], ah0, bh[2], bh[3]);
                mma16816(cc[0][nb + 1], ah0, bl[2], bl[3]);
                mma16816(cc[0][nb + 1], al0, bh[2], bh[3]);
                mma16816(cc[1][nb],     ah1, bh[0], bh[1]);
                mma16816(cc[1][nb],     ah1, bl[0], bl[1]);
                mma16816(cc[1][nb],     al1, bh[0], bh[1]);
                mma16816(cc[1][nb + 1], ah1, bh[2], bh[3]);
                mma16816(cc[1][nb + 1], ah1, bl[2], bl[3]);
                mma16816(cc[1][nb + 1], al1, bh[2], bh[3]);
            }
        }
        __syncthreads();
    }

    // ---------------- split yk/yq -> GEMM2 tiles [128][72] ----------------
    {
        const uint32_t HIb = mat ? YQ2HI : YK2HI, LOb = HIb + 9216u;
        const int r0 = mrow0 + (lane >> 2), cb = (lane & 3) * 2;
        #pragma unroll
        for (int rt = 0; rt < 2; rt++) {
            const int rr = r0 + rt * 16;
            #pragma unroll
            for (int nt = 0; nt < 8; nt++) {
                const int col = nt * 8 + cb;
                uint32_t hi, lo;
                split2(cc[rt][nt][0], cc[rt][nt][1], hi, lo);
                *(uint32_t*)&smem[HIb + (uint32_t)(rr * PITCH + col)] = hi;
                *(uint32_t*)&smem[LOb + (uint32_t)(rr * PITCH + col)] = lo;
                split2(cc[rt][nt][2], cc[rt][nt][3], hi, lo);
                *(uint32_t*)&smem[HIb + (uint32_t)((rr + 8) * PITCH + col)] = hi;
                *(uint32_t*)&smem[LOb + (uint32_t)((rr + 8) * PITCH + col)] = lo;
            }
        }
    }
    __syncthreads();

    // ---------------- GEMM2: M_s = yk_s @ yq_s^T per segment s ----------------
    float cm[8][4];
    #pragma unroll
    for (int n = 0; n < 8; n++)
        #pragma unroll
        for (int j = 0; j < 4; j++) cm[n][j] = 0.0f;
    const int seg = wid >> 2, rt = wid & 3;
    {
        #pragma unroll
        for (int ks = 0; ks < 4; ks++) {
            uint32_t Ah[4], Al[4];
            const uint32_t at = (uint32_t)((seg * 64 + rt * 16) * PITCH + ks * 16);
            ldsm4(Ah, addr72(sb, YK2HI + at, lane));
            ldsm4(Al, addr72(sb, YK2LO + at, lane));
            #pragma unroll
            for (int np = 0; np < 4; np++) {
                const uint32_t bt = (uint32_t)((seg * 64 + np * 16) * PITCH + ks * 16);
                uint32_t Bh[4], Bl[4];
                ldsm4(Bh, addr72(sb, YQ2HI + bt, lane));
                ldsm4(Bl, addr72(sb, YQ2LO + bt, lane));
                const int nb = np * 2;
                mma16816(cm[nb],     Ah, Bh[0], Bh[2]);
                mma16816(cm[nb],     Ah, Bl[0], Bl[2]);
                mma16816(cm[nb],     Al, Bh[0], Bh[2]);
                mma16816(cm[nb + 1], Ah, Bh[1], Bh[3]);
                mma16816(cm[nb + 1], Ah, Bl[1], Bl[3]);
                mma16816(cm[nb + 1], Al, Bh[1], Bh[3]);
            }
        }
    }
    __syncthreads();   // all GEMM2 tile reads done; logits may alias tiles

    // ---------------- scaled logits -> fp32 [128][68] at smem base ----------------
    float* attnf = (float*)smem;
    {
        const int r0 = seg * 64 + rt * 16 + (lane >> 2);
        const int cb = (lane & 3) * 2;
        #pragma unroll
        for (int nt = 0; nt < 8; nt++) {
            const int col = nt * 8 + cb;
            *(float2*)&attnf[r0 * FPITCH + col] =
                make_float2(cm[nt][0] * 0.125f, cm[nt][1] * 0.125f);
            *(float2*)&attnf[(r0 + 8) * FPITCH + col] =
                make_float2(cm[nt][2] * 0.125f, cm[nt][3] * 0.125f);
        }
    }
    __syncthreads();

    // ---------------- row softmax + EPS (8 warps x 16 rows) ----------------
    #pragma unroll 1
    for (int rr = 0; rr < 16; rr++) {
        const int r = wid * 16 + rr;
        float v0 = attnf[r * FPITCH + lane];
        float v1 = attnf[r * FPITCH + lane + 32];
        float mx = fmaxf(v0, v1);
        #pragma unroll
        for (int o = 16; o > 0; o >>= 1)
            mx = fmaxf(mx, __shfl_xor_sync(0xffffffffu, mx, o));
        float e0 = __expf(v0 - mx);
        float e1 = __expf(v1 - mx);
        float s = e0 + e1;
        #pragma unroll
        for (int o = 16; o > 0; o >>= 1)
            s += __shfl_xor_sync(0xffffffffu, s, o);
        const float inv = 1.0f / s;
        attnf[r * FPITCH + lane]      = e0 * inv + 1e-6f;
        attnf[r * FPITCH + lane + 32] = e1 * inv + 1e-6f;
    }
    __syncthreads();

    // ---------------- column sums (per segment) + normalize + store ----------------
    {
        const int q = tid & 1;                 // row half within segment
        const int sc2 = tid >> 1;              // 0..127 = seg*64 + col
        const int s = sc2 >> 6, col = sc2 & 63;
        float su = 0.0f;
        #pragma unroll
        for (int l = 0; l < 32; l++) su += attnf[(s * 64 + q * 32 + l) * FPITCH + col];
        part[q][sc2] = su;
    }
    __syncthreads();
    if (tid < 128) csum_inv[tid] = 1.0f / (part[0][tid] + part[1][tid]);
    __syncthreads();

    {
        float* outb = out + (long)blockIdx.x * 8192;
        #pragma unroll
        for (int e = 0; e < 8; e++) {
            const int f4 = e * 256 + tid;       // 0..2047
            const int l = f4 >> 4, m0 = (f4 & 15) * 4;
            float4 v = *(const float4*)&attnf[l * FPITCH + m0];
            const int ci = (l >> 6) * 64 + m0;
            v.x *= csum_inv[ci + 0];
            v.y *= csum_inv[ci + 1];
            v.z *= csum_inv[ci + 2];
            v.w *= csum_inv[ci + 3];
            *(float4*)&outb[l * 64 + m0] = v;   // [seg][l&63][64] is contiguous
        }
    }
}

extern "C" void kernel_launch(void* const* d_in, const int* in_sizes, int n_in,
                              void* d_out, int out_size) {
    const float* yhat = (const float*)d_in[0];
    const float* y    = (const float*)d_in[1];
    const float* kmat = (const float*)d_in[2];
    const float* qmat = (const float*)d_in[3];
    float* out = (float*)d_out;

    const int N = in_sizes[1] / HDIM;
    const int grid = N / 128;                 // 2 segments per CTA

    split_kq_kernel<<<128, 256>>>(kmat, qmat);

    cudaFuncSetAttribute(cross_att_m128,
                         cudaFuncAttributeMaxDynamicSharedMemorySize, (int)SMEM_BYTES);
    cudaFuncSetAttribute(cross_att_m128,
                         cudaFuncAttributePreferredSharedMemoryCarveout, 100);
    cross_att_m128<<<grid, 256, SMEM_BYTES>>>(yhat, y, out);
}

// round 7
// speedup vs baseline: 1.0544x; 1.0471x over previous
#include <cuda_runtime.h>
#include <cuda_fp16.h>
#include <cstdint>

// CrossAttUnit fused — fp16-split (Ootomo) warp MMA, 8-warp CTA (R4 skeleton)
// + schedulable (non-volatile) MMAs with interleaved accumulator chains.
// N=262144, H=256, D=64, L=64, B=4096. 1 segment per CTA, 256 threads, 3 CTAs/SM.

#define HDIM 256
#define PITCH 72            // smem half pitch per tile row (conflict-free LDSM)
#define FPITCH 68           // fp32 logits/attn pitch

// smem half-index offsets
#define AY_HI 0u
#define AY_LO 4608u
#define AH_HI 9216u
#define AH_LO 13824u
#define B_BASE 18432u       // 4 bufs of 4608 halfs: GEMM1 = bKhi,bKlo,bQhi,bQlo; GEMM2 = ykhi,yklo,yqhi,yqlo
#define SMEM_HALFS 36864u   // 73728 bytes dynamic

__device__ __align__(16) __half g_b[2 * 2 * 256 * 64];  // [mat*2+split][k][n]

__global__ void split_kq_kernel(const float* __restrict__ kmat,
                                const float* __restrict__ qmat) {
    int gid = blockIdx.x * 256 + threadIdx.x;        // 32768
    int mat = gid >> 14, k = (gid >> 6) & 255, n = gid & 63;
    float x = mat ? qmat[k * 64 + n] : kmat[k * 64 + n];
    __half hi = __float2half_rn(x);
    __half lo = __float2half_rn(x - __half2float(hi));
    g_b[(mat * 2 + 0) * 16384 + k * 64 + n] = hi;
    g_b[(mat * 2 + 1) * 16384 + k * 64 + n] = lo;
}

__device__ __forceinline__ uint32_t smem_u32(const void* p) {
    uint32_t a;
    asm("{ .reg .u64 t; cvta.to.shared.u64 t, %1; cvt.u32.u64 %0, t; }" : "=r"(a) : "l"(p));
    return a;
}
__device__ __forceinline__ void ldsm4(uint32_t r[4], uint32_t addr) {
    asm volatile("ldmatrix.sync.aligned.m8n8.x4.shared.b16 {%0,%1,%2,%3}, [%4];"
                 : "=r"(r[0]), "=r"(r[1]), "=r"(r[2]), "=r"(r[3]) : "r"(addr));
}
__device__ __forceinline__ void ldsm4t(uint32_t r[4], uint32_t addr) {
    asm volatile("ldmatrix.sync.aligned.m8n8.x4.trans.shared.b16 {%0,%1,%2,%3}, [%4];"
                 : "=r"(r[0]), "=r"(r[1]), "=r"(r[2]), "=r"(r[3]) : "r"(addr));
}
// NOTE: non-volatile — pure register dataflow; lets ptxas pipeline HMMA chains.
__device__ __forceinline__ void mma16816(float c[4], const uint32_t a[4],
                                         uint32_t b0, uint32_t b1) {
    asm("mma.sync.aligned.m16n8k16.row.col.f32.f16.f16.f32 "
        "{%0,%1,%2,%3},{%4,%5,%6,%7},{%8,%9},{%0,%1,%2,%3};"
        : "+f"(c[0]), "+f"(c[1]), "+f"(c[2]), "+f"(c[3])
        : "r"(a[0]), "r"(a[1]), "r"(a[2]), "r"(a[3]), "r"(b0), "r"(b1));
}
__device__ __forceinline__ void split2(float x0, float x1, uint32_t& hi, uint32_t& lo) {
    __half h0 = __float2half_rn(x0), h1 = __float2half_rn(x1);
    __half l0 = __float2half_rn(x0 - __half2float(h0));
    __half l1 = __float2half_rn(x1 - __half2float(h1));
    __half2 H = __halves2half2(h0, h1), L = __halves2half2(l0, l1);
    hi = *(uint32_t*)&H;
    lo = *(uint32_t*)&L;
}
__device__ __forceinline__ uint32_t addrA(uint32_t sb, uint32_t tile_halfs, int lane) {
    int row = lane & 15, colh = (lane >> 4) << 3;
    return sb + (tile_halfs + row * PITCH + colh) * 2;
}
__device__ __forceinline__ uint32_t addrBt(uint32_t sb, uint32_t tile_halfs, int lane) {
    int q = lane >> 3, i = lane & 7;
    int k = i + ((q & 1) << 3), n = (q >> 1) << 3;
    return sb + (tile_halfs + k * PITCH + n) * 2;
}

#define CP_ASYNC16(saddr, gptr) \
    asm volatile("cp.async.cg.shared.global [%0], [%1], 16;" :: "r"(saddr), "l"(gptr) : "memory")
#define CP_COMMIT() asm volatile("cp.async.commit_group;" ::: "memory")
#define CP_WAIT0()  asm volatile("cp.async.wait_group 0;" ::: "memory")

__global__ __launch_bounds__(256, 3)
void cross_att_hmma9(const float* __restrict__ yhat,
                     const float* __restrict__ y,
                     float* __restrict__ out) {
    extern __shared__ __half smem[];
    const uint32_t sb = smem_u32(smem);
    const int tid = threadIdx.x, wid = tid >> 5, lane = tid & 31;
    __shared__ float part[4][64];
    __shared__ float csum_inv[64];

    const long rowbase = (long)blockIdx.x * 64;
    const int mat = wid >> 2;            // 0: yk (y, k) ; 1: yq (yhat, q)
    const int rt  = wid & 3;             // row tile (16 rows)

    float cc[8][4];
    #pragma unroll
    for (int n = 0; n < 8; n++)
        #pragma unroll
        for (int j = 0; j < 4; j++) cc[n][j] = 0.0f;

    const uint32_t A_HI = mat ? AH_HI : AY_HI;
    const uint32_t A_LO = mat ? AH_LO : AY_LO;
    const uint32_t Bb_HI = B_BASE + (mat ? 2u : 0u) * 4608u;
    const uint32_t Bb_LO = Bb_HI + 4608u;

    // ---------------- GEMM1: yk = y@k, yq = yhat@q ; K streamed in 4 chunks ----------------
    #pragma unroll 1
    for (int c = 0; c < 4; c++) {
        // B tiles via cp.async (pre-split fp16)
        #pragma unroll
        for (int t = 0; t < 8; t++) {
            const int idx = tid + t * 256;          // 0..2047
            const int buf = idx >> 9, rem = idx & 511;
            const int row = rem >> 3, u4 = rem & 7;
            const uint32_t sa = sb + (B_BASE + buf * 4608u + (uint32_t)(row * PITCH + u4 * 8)) * 2;
            CP_ASYNC16(sa, &g_b[buf * 16384 + (c * 64 + row) * 64 + u4 * 8]);
        }
        CP_COMMIT();
        // A: y / yhat chunk fp32 -> hi/lo fp16 (through registers)
        #pragma unroll
        for (int t = 0; t < 4; t++) {
            const int idx = tid + t * 256;          // 0..1023
            const int row = idx >> 4, c4 = idx & 15;
            const long g = (rowbase + row) * HDIM + c * 64 + c4 * 4;
            float4 vy = *(const float4*)&y[g];
            float4 vh = *(const float4*)&yhat[g];
            uint2 yh, yl, hh, hl;
            split2(vy.x, vy.y, yh.x, yl.x); split2(vy.z, vy.w, yh.y, yl.y);
            split2(vh.x, vh.y, hh.x, hl.x); split2(vh.z, vh.w, hh.y, hl.y);
            const uint32_t so = (uint32_t)(row * PITCH + c4 * 4);
            *(uint2*)&smem[AY_HI + so] = yh;
            *(uint2*)&smem[AY_LO + so] = yl;
            *(uint2*)&smem[AH_HI + so] = hh;
            *(uint2*)&smem[AH_LO + so] = hl;
        }
        CP_WAIT0();
        __syncthreads();

        #pragma unroll
        for (int ks = 0; ks < 4; ks++) {
            uint32_t ah[4], al[4];
            const uint32_t at = (uint32_t)(rt * 16 * PITCH + ks * 16);
            ldsm4(ah, addrA(sb, A_HI + at, lane));
            ldsm4(al, addrA(sb, A_LO + at, lane));
            #pragma unroll
            for (int np = 0; np < 4; np++) {
                const uint32_t bt = (uint32_t)(ks * 16 * PITCH + np * 16);
                uint32_t bh[4], bl[4];
                ldsm4t(bh, addrBt(sb, Bb_HI + bt, lane));
                ldsm4t(bl, addrBt(sb, Bb_LO + bt, lane));
                const int nb = 2 * np;
                // interleave the two accumulator chains (order within each acc: hh, hl, lh)
                mma16816(cc[nb],     ah, bh[0], bh[1]);
                mma16816(cc[nb + 1], ah, bh[2], bh[3]);
                mma16816(cc[nb],     ah, bl[0], bl[1]);
                mma16816(cc[nb + 1], ah, bl[2], bl[3]);
                mma16816(cc[nb],     al, bh[0], bh[1]);
                mma16816(cc[nb + 1], al, bh[2], bh[3]);
            }
        }
        __syncthreads();
    }

    // ---------------- split yk/yq -> B region (yk: bufs 0/1, yq: bufs 2/3) ----------------
    {
        const int r0 = rt * 16 + (lane >> 2);
        const int col = (lane & 3) * 2;
        const uint32_t HIb = B_BASE + (mat ? 2u : 0u) * 4608u;
        const uint32_t LOb = HIb + 4608u;
        #pragma unroll
        for (int nt = 0; nt < 8; nt++) {
            uint32_t hi, lo;
            split2(cc[nt][0], cc[nt][1], hi, lo);
            *(uint32_t*)&smem[HIb + (uint32_t)(r0 * PITCH + nt * 8 + col)] = hi;
            *(uint32_t*)&smem[LOb + (uint32_t)(r0 * PITCH + nt * 8 + col)] = lo;
            split2(cc[nt][2], cc[nt][3], hi, lo);
            *(uint32_t*)&smem[HIb + (uint32_t)((r0 + 8) * PITCH + nt * 8 + col)] = hi;
            *(uint32_t*)&smem[LOb + (uint32_t)((r0 + 8) * PITCH + nt * 8 + col)] = lo;
        }
    }
    __syncthreads();

    // ---------------- GEMM2: M = yk @ yq^T ; warp = (row tile rt, col half ch) ----------------
    float* attnf = (float*)smem;                 // logits [64][FPITCH], aliases A region
    {
        const int ch = wid >> 2;                 // 0 or 1 -> cols ch*32..+32
        const int ct = ch * 32;
        float cm[4][4];
        #pragma unroll
        for (int n = 0; n < 4; n++)
            #pragma unroll
            for (int j = 0; j < 4; j++) cm[n][j] = 0.0f;

        #pragma unroll
        for (int ks = 0; ks < 4; ks++) {
            uint32_t Ah[4], Al[4];
            const uint32_t at = (uint32_t)(rt * 16 * PITCH + ks * 16);
            ldsm4(Ah, addrA(sb, B_BASE + 0u * 4608u + at, lane));
            ldsm4(Al, addrA(sb, B_BASE + 1u * 4608u + at, lane));
            #pragma unroll
            for (int nl = 0; nl < 2; nl++) {
                const uint32_t bt = (uint32_t)((ct + nl * 16) * PITCH + ks * 16);
                uint32_t Bh[4], Bl[4];
                ldsm4(Bh, addrA(sb, B_BASE + 2u * 4608u + bt, lane));
                ldsm4(Bl, addrA(sb, B_BASE + 3u * 4608u + bt, lane));
                const int nb = 2 * nl;
                mma16816(cm[nb],     Ah, Bh[0], Bh[2]);
                mma16816(cm[nb + 1], Ah, Bh[1], Bh[3]);
                mma16816(cm[nb],     Ah, Bl[0], Bl[2]);
                mma16816(cm[nb + 1], Ah, Bl[1], Bl[3]);
                mma16816(cm[nb],     Al, Bh[0], Bh[2]);
                mma16816(cm[nb + 1], Al, Bh[1], Bh[3]);
            }
        }
        __syncthreads();   // A region free; write scaled logits

        const int r0 = rt * 16 + (lane >> 2);
        const int cb = (lane & 3) * 2;
        #pragma unroll
        for (int nt = 0; nt < 4; nt++) {
            const int colb = ct + nt * 8 + cb;
            *(float2*)&attnf[r0 * FPITCH + colb] =
                make_float2(cm[nt][0] * 0.125f, cm[nt][1] * 0.125f);
            *(float2*)&attnf[(r0 + 8) * FPITCH + colb] =
                make_float2(cm[nt][2] * 0.125f, cm[nt][3] * 0.125f);
        }
    }
    __syncthreads();

    // ---------------- row softmax + EPS (8 warps x 8 rows) ----------------
    #pragma unroll 1
    for (int rr = 0; rr < 8; rr++) {
        const int r = wid * 8 + rr;
        float v0 = attnf[r * FPITCH + lane];
        float v1 = attnf[r * FPITCH + lane + 32];
        float mx = fmaxf(v0, v1);
        #pragma unroll
        for (int o = 16; o > 0; o >>= 1)
            mx = fmaxf(mx, __shfl_xor_sync(0xffffffffu, mx, o));
        float e0 = __expf(v0 - mx);
        float e1 = __expf(v1 - mx);
        float s = e0 + e1;
        #pragma unroll
        for (int o = 16; o > 0; o >>= 1)
            s += __shfl_xor_sync(0xffffffffu, s, o);
        const float inv = 1.0f / s;
        attnf[r * FPITCH + lane]      = e0 * inv + 1e-6f;
        attnf[r * FPITCH + lane + 32] = e1 * inv + 1e-6f;
    }
    __syncthreads();

    // ---------------- column sums (4-way parallel) + normalize + store ----------------
    {
        const int col = tid & 63, q = tid >> 6;
        float s = 0.0f;
        #pragma unroll
        for (int l = 0; l < 16; l++) s += attnf[(q * 16 + l) * FPITCH + col];
        part[q][col] = s;
    }
    __syncthreads();
    if (tid < 64)
        csum_inv[tid] = 1.0f / (part[0][tid] + part[1][tid] + part[2][tid] + part[3][tid]);
    __syncthreads();

    {
        float* outb = out + (long)blockIdx.x * 4096;
        #pragma unroll
        for (int e = 0; e < 4; e++) {
            const int f4 = e * 256 + tid;
            const int l = f4 >> 4, m0 = (f4 & 15) * 4;
            float4 v = *(const float4*)&attnf[l * FPITCH + m0];
            v.x *= csum_inv[m0 + 0];
            v.y *= csum_inv[m0 + 1];
            v.z *= csum_inv[m0 + 2];
            v.w *= csum_inv[m0 + 3];
            *(float4*)&outb[l * 64 + m0] = v;
        }
    }
}

extern "C" void kernel_launch(void* const* d_in, const int* in_sizes, int n_in,
                              void* d_out, int out_size) {
    const float* yhat = (const float*)d_in[0];
    const float* y    = (const float*)d_in[1];
    const float* kmat = (const float*)d_in[2];
    const float* qmat = (const float*)d_in[3];
    float* out = (float*)d_out;

    const int N = in_sizes[1] / HDIM;
    const int grid = N / 64;                 // 1 segment per CTA

    split_kq_kernel<<<128, 256>>>(kmat, qmat);

    const size_t smem_bytes = SMEM_HALFS * sizeof(__half);   // 73728
    cudaFuncSetAttribute(cross_att_hmma9,
                         cudaFuncAttributeMaxDynamicSharedMemorySize, (int)smem_bytes);
    cudaFuncSetAttribute(cross_att_hmma9,
                         cudaFuncAttributePreferredSharedMemoryCarveout, 100);
    cross_att_hmma9<<<grid, 256, smem_bytes>>>(yhat, y, out);
}

// round 8
// speedup vs baseline: 1.0911x; 1.0348x over previous
#include <cuda_runtime.h>
#include <cuda_fp16.h>
#include <cstdint>

// CrossAttUnit fused — fp16-split (Ootomo) warp MMA, 8-warp CTA, 32x32 GEMM1 tiles.
// N=262144, H=256, D=64, L=64, B=4096. 1 segment per CTA, 256 threads, 3 CTAs/SM.

#define HDIM 256
#define PITCH 72            // smem half pitch per tile row (conflict-free LDSM)
#define FPITCH 68           // fp32 logits/attn pitch

// smem half-index offsets
#define AY_HI 0u
#define AY_LO 4608u
#define AH_HI 9216u
#define AH_LO 13824u
#define B_BASE 18432u       // 4 bufs of 4608 halfs: GEMM1 = bKhi,bKlo,bQhi,bQlo; GEMM2 = ykhi,yklo,yqhi,yqlo
#define SMEM_HALFS 36864u   // 73728 bytes dynamic

__device__ __align__(16) __half g_b[2 * 2 * 256 * 64];  // [mat*2+split][k][n]

__global__ void split_kq_kernel(const float* __restrict__ kmat,
                                const float* __restrict__ qmat) {
    int gid = blockIdx.x * 256 + threadIdx.x;        // 32768
    int mat = gid >> 14, k = (gid >> 6) & 255, n = gid & 63;
    float x = mat ? qmat[k * 64 + n] : kmat[k * 64 + n];
    __half hi = __float2half_rn(x);
    __half lo = __float2half_rn(x - __half2float(hi));
    g_b[(mat * 2 + 0) * 16384 + k * 64 + n] = hi;
    g_b[(mat * 2 + 1) * 16384 + k * 64 + n] = lo;
}

__device__ __forceinline__ uint32_t smem_u32(const void* p) {
    uint32_t a;
    asm("{ .reg .u64 t; cvta.to.shared.u64 t, %1; cvt.u32.u64 %0, t; }" : "=r"(a) : "l"(p));
    return a;
}
__device__ __forceinline__ void ldsm4(uint32_t r[4], uint32_t addr) {
    asm volatile("ldmatrix.sync.aligned.m8n8.x4.shared.b16 {%0,%1,%2,%3}, [%4];"
                 : "=r"(r[0]), "=r"(r[1]), "=r"(r[2]), "=r"(r[3]) : "r"(addr));
}
__device__ __forceinline__ void ldsm4t(uint32_t r[4], uint32_t addr) {
    asm volatile("ldmatrix.sync.aligned.m8n8.x4.trans.shared.b16 {%0,%1,%2,%3}, [%4];"
                 : "=r"(r[0]), "=r"(r[1]), "=r"(r[2]), "=r"(r[3]) : "r"(addr));
}
// non-volatile — pure register dataflow; lets ptxas pipeline HMMA chains
__device__ __forceinline__ void mma16816(float c[4], const uint32_t a[4],
                                         uint32_t b0, uint32_t b1) {
    asm("mma.sync.aligned.m16n8k16.row.col.f32.f16.f16.f32 "
        "{%0,%1,%2,%3},{%4,%5,%6,%7},{%8,%9},{%0,%1,%2,%3};"
        : "+f"(c[0]), "+f"(c[1]), "+f"(c[2]), "+f"(c[3])
        : "r"(a[0]), "r"(a[1]), "r"(a[2]), "r"(a[3]), "r"(b0), "r"(b1));
}
__device__ __forceinline__ void split2(float x0, float x1, uint32_t& hi, uint32_t& lo) {
    __half h0 = __float2half_rn(x0), h1 = __float2half_rn(x1);
    __half l0 = __float2half_rn(x0 - __half2float(h0));
    __half l1 = __float2half_rn(x1 - __half2float(h1));
    __half2 H = __halves2half2(h0, h1), L = __halves2half2(l0, l1);
    hi = *(uint32_t*)&H;
    lo = *(uint32_t*)&L;
}
__device__ __forceinline__ uint32_t addrA(uint32_t sb, uint32_t tile_halfs, int lane) {
    int row = lane & 15, colh = (lane >> 4) << 3;
    return sb + (tile_halfs + row * PITCH + colh) * 2;
}
__device__ __forceinline__ uint32_t addrBt(uint32_t sb, uint32_t tile_halfs, int lane) {
    int q = lane >> 3, i = lane & 7;
    int k = i + ((q & 1) << 3), n = (q >> 1) << 3;
    return sb + (tile_halfs + k * PITCH + n) * 2;
}

#define CP_ASYNC16(saddr, gptr) \
    asm volatile("cp.async.cg.shared.global [%0], [%1], 16;" :: "r"(saddr), "l"(gptr) : "memory")
#define CP_COMMIT() asm volatile("cp.async.commit_group;" ::: "memory")
#define CP_WAIT0()  asm volatile("cp.async.wait_group 0;" ::: "memory")

__global__ __launch_bounds__(256, 3)
void cross_att_hmma10(const float* __restrict__ yhat,
                      const float* __restrict__ y,
                      float* __restrict__ out) {
    extern __shared__ __half smem[];
    const uint32_t sb = smem_u32(smem);
    const int tid = threadIdx.x, wid = tid >> 5, lane = tid & 31;
    __shared__ float part[4][64];
    __shared__ float csum_inv[64];

    const long rowbase = (long)blockIdx.x * 64;
    const int mat = wid >> 2;                // 0: yk (y,k) ; 1: yq (yhat,q)
    const int w2 = wid & 3;
    const int mrow0 = (w2 & 1) * 32;         // warp's 32-row block
    const int ncol0 = (w2 >> 1) * 32;        // warp's 32-col block

    // cc[mtile 0/1][n8 0..3][4]
    float cc[2][4][4];
    #pragma unroll
    for (int a = 0; a < 2; a++)
        #pragma unroll
        for (int b = 0; b < 4; b++)
            #pragma unroll
            for (int j = 0; j < 4; j++) cc[a][b][j] = 0.0f;

    const uint32_t A_HI = mat ? AH_HI : AY_HI;
    const uint32_t A_LO = mat ? AH_LO : AY_LO;
    const uint32_t Bb_HI = B_BASE + (mat ? 2u : 0u) * 4608u;
    const uint32_t Bb_LO = Bb_HI + 4608u;

    // ---------------- GEMM1: yk = y@k, yq = yhat@q ; K streamed in 4 chunks ----------------
    #pragma unroll 1
    for (int c = 0; c < 4; c++) {
        // B tiles via cp.async (pre-split fp16)
        #pragma unroll
        for (int t = 0; t < 8; t++) {
            const int idx = tid + t * 256;          // 0..2047
            const int buf = idx >> 9, rem = idx & 511;
            const int row = rem >> 3, u4 = rem & 7;
            const uint32_t sa = sb + (B_BASE + buf * 4608u + (uint32_t)(row * PITCH + u4 * 8)) * 2;
            CP_ASYNC16(sa, &g_b[buf * 16384 + (c * 64 + row) * 64 + u4 * 8]);
        }
        CP_COMMIT();
        // A: y / yhat chunk fp32 -> hi/lo fp16 (through registers)
        #pragma unroll
        for (int t = 0; t < 4; t++) {
            const int idx = tid + t * 256;          // 0..1023
            const int row = idx >> 4, c4 = idx & 15;
            const long g = (rowbase + row) * HDIM + c * 64 + c4 * 4;
            float4 vy = *(const float4*)&y[g];
            float4 vh = *(const float4*)&yhat[g];
            uint2 yh, yl, hh, hl;
            split2(vy.x, vy.y, yh.x, yl.x); split2(vy.z, vy.w, yh.y, yl.y);
            split2(vh.x, vh.y, hh.x, hl.x); split2(vh.z, vh.w, hh.y, hl.y);
            const uint32_t so = (uint32_t)(row * PITCH + c4 * 4);
            *(uint2*)&smem[AY_HI + so] = yh;
            *(uint2*)&smem[AY_LO + so] = yl;
            *(uint2*)&smem[AH_HI + so] = hh;
            *(uint2*)&smem[AH_LO + so] = hl;
        }
        CP_WAIT0();
        __syncthreads();

        #pragma unroll
        for (int ks = 0; ks < 4; ks++) {
            uint32_t ah0[4], al0[4], ah1[4], al1[4];
            const uint32_t at0 = (uint32_t)(mrow0 * PITCH + ks * 16);
            const uint32_t at1 = (uint32_t)((mrow0 + 16) * PITCH + ks * 16);
            ldsm4(ah0, addrA(sb, A_HI + at0, lane));
            ldsm4(al0, addrA(sb, A_LO + at0, lane));
            ldsm4(ah1, addrA(sb, A_HI + at1, lane));
            ldsm4(al1, addrA(sb, A_LO + at1, lane));
            #pragma unroll
            for (int nt = 0; nt < 2; nt++) {
                const uint32_t bt = (uint32_t)(ks * 16 * PITCH + ncol0 + nt * 16);
                uint32_t bh[4], bl[4];
                ldsm4t(bh, addrBt(sb, Bb_HI + bt, lane));
                ldsm4t(bl, addrBt(sb, Bb_LO + bt, lane));
                const int nb = 2 * nt;
                // order within each accumulator: hh, hl, lh (matches prior rounds)
                mma16816(cc[0][nb],     ah0, bh[0], bh[1]);
                mma16816(cc[0][nb + 1], ah0, bh[2], bh[3]);
                mma16816(cc[1][nb],     ah1, bh[0], bh[1]);
                mma16816(cc[1][nb + 1], ah1, bh[2], bh[3]);
                mma16816(cc[0][nb],     ah0, bl[0], bl[1]);
                mma16816(cc[0][nb + 1], ah0, bl[2], bl[3]);
                mma16816(cc[1][nb],     ah1, bl[0], bl[1]);
                mma16816(cc[1][nb + 1], ah1, bl[2], bl[3]);
                mma16816(cc[0][nb],     al0, bh[0], bh[1]);
                mma16816(cc[0][nb + 1], al0, bh[2], bh[3]);
                mma16816(cc[1][nb],     al1, bh[0], bh[1]);
                mma16816(cc[1][nb + 1], al1, bh[2], bh[3]);
            }
        }
        __syncthreads();
    }

    // ---------------- split yk/yq -> B region (yk: bufs 0/1, yq: bufs 2/3) ----------------
    {
        const uint32_t HIb = B_BASE + (mat ? 2u : 0u) * 4608u;
        const uint32_t LOb = HIb + 4608u;
        const int rbase = mrow0 + (lane >> 2);
        const int cbase = ncol0 + (lane & 3) * 2;
        #pragma unroll
        for (int mt = 0; mt < 2; mt++) {
            const int r0 = rbase + mt * 16;
            #pragma unroll
            for (int nt = 0; nt < 4; nt++) {
                const int col = cbase + nt * 8;
                uint32_t hi, lo;
                split2(cc[mt][nt][0], cc[mt][nt][1], hi, lo);
                *(uint32_t*)&smem[HIb + (uint32_t)(r0 * PITCH + col)] = hi;
                *(uint32_t*)&smem[LOb + (uint32_t)(r0 * PITCH + col)] = lo;
                split2(cc[mt][nt][2], cc[mt][nt][3], hi, lo);
                *(uint32_t*)&smem[HIb + (uint32_t)((r0 + 8) * PITCH + col)] = hi;
                *(uint32_t*)&smem[LOb + (uint32_t)((r0 + 8) * PITCH + col)] = lo;
            }
        }
    }
    __syncthreads();

    // ---------------- GEMM2: M = yk @ yq^T ; warp = (row tile rt, col half ch) ----------------
    float* attnf = (float*)smem;                 // logits [64][FPITCH], aliases A region
    {
        const int rt = wid & 3;
        const int ch = wid >> 2;
        const int ct = ch * 32;
        float cm[4][4];
        #pragma unroll
        for (int n = 0; n < 4; n++)
            #pragma unroll
            for (int j = 0; j < 4; j++) cm[n][j] = 0.0f;

        #pragma unroll
        for (int ks = 0; ks < 4; ks++) {
            uint32_t Ah[4], Al[4];
            const uint32_t at = (uint32_t)(rt * 16 * PITCH + ks * 16);
            ldsm4(Ah, addrA(sb, B_BASE + 0u * 4608u + at, lane));
            ldsm4(Al, addrA(sb, B_BASE + 1u * 4608u + at, lane));
            #pragma unroll
            for (int nl = 0; nl < 2; nl++) {
                const uint32_t bt = (uint32_t)((ct + nl * 16) * PITCH + ks * 16);
                uint32_t Bh[4], Bl[4];
                ldsm4(Bh, addrA(sb, B_BASE + 2u * 4608u + bt, lane));
                ldsm4(Bl, addrA(sb, B_BASE + 3u * 4608u + bt, lane));
                const int nb = 2 * nl;
                mma16816(cm[nb],     Ah, Bh[0], Bh[2]);
                mma16816(cm[nb + 1], Ah, Bh[1], Bh[3]);
                mma16816(cm[nb],     Ah, Bl[0], Bl[2]);
                mma16816(cm[nb + 1], Ah, Bl[1], Bl[3]);
                mma16816(cm[nb],     Al, Bh[0], Bh[2]);
                mma16816(cm[nb + 1], Al, Bh[1], Bh[3]);
            }
        }
        __syncthreads();   // A region free; write scaled logits

        const int r0 = rt * 16 + (lane >> 2);
        const int cb = (lane & 3) * 2;
        #pragma unroll
        for (int nt = 0; nt < 4; nt++) {
            const int colb = ct + nt * 8 + cb;
            *(float2*)&attnf[r0 * FPITCH + colb] =
                make_float2(cm[nt][0] * 0.125f, cm[nt][1] * 0.125f);
            *(float2*)&attnf[(r0 + 8) * FPITCH + colb] =
                make_float2(cm[nt][2] * 0.125f, cm[nt][3] * 0.125f);
        }
    }
    __syncthreads();

    // ---------------- row softmax + EPS (8 warps x 8 rows) ----------------
    #pragma unroll 1
    for (int rr = 0; rr < 8; rr++) {
        const int r = wid * 8 + rr;
        float v0 = attnf[r * FPITCH + lane];
        float v1 = attnf[r * FPITCH + lane + 32];
        float mx = fmaxf(v0, v1);
        #pragma unroll
        for (int o = 16; o > 0; o >>= 1)
            mx = fmaxf(mx, __shfl_xor_sync(0xffffffffu, mx, o));
        float e0 = __expf(v0 - mx);
        float e1 = __expf(v1 - mx);
        float s = e0 + e1;
        #pragma unroll
        for (int o = 16; o > 0; o >>= 1)
            s += __shfl_xor_sync(0xffffffffu, s, o);
        const float inv = 1.0f / s;
        attnf[r * FPITCH + lane]      = e0 * inv + 1e-6f;
        attnf[r * FPITCH + lane + 32] = e1 * inv + 1e-6f;
    }
    __syncthreads();

    // ---------------- column sums (4-way parallel) + normalize + store ----------------
    {
        const int col = tid & 63, q = tid >> 6;
        float s = 0.0f;
        #pragma unroll
        for (int l = 0; l < 16; l++) s += attnf[(q * 16 + l) * FPITCH + col];
        part[q][col] = s;
    }
    __syncthreads();
    if (tid < 64)
        csum_inv[tid] = 1.0f / (part[0][tid] + part[1][tid] + part[2][tid] + part[3][tid]);
    __syncthreads();

    {
        float* outb = out + (long)blockIdx.x * 4096;
        #pragma unroll
        for (int e = 0; e < 4; e++) {
            const int f4 = e * 256 + tid;
            const int l = f4 >> 4, m0 = (f4 & 15) * 4;
            float4 v = *(const float4*)&attnf[l * FPITCH + m0];
            v.x *= csum_inv[m0 + 0];
            v.y *= csum_inv[m0 + 1];
            v.z *= csum_inv[m0 + 2];
            v.w *= csum_inv[m0 + 3];
            *(float4*)&outb[l * 64 + m0] = v;
        }
    }
}

extern "C" void kernel_launch(void* const* d_in, const int* in_sizes, int n_in,
                              void* d_out, int out_size) {
    const float* yhat = (const float*)d_in[0];
    const float* y    = (const float*)d_in[1];
    const float* kmat = (const float*)d_in[2];
    const float* qmat = (const float*)d_in[3];
    float* out = (float*)d_out;

    const int N = in_sizes[1] / HDIM;
    const int grid = N / 64;                 // 1 segment per CTA

    split_kq_kernel<<<128, 256>>>(kmat, qmat);

    const size_t smem_bytes = SMEM_HALFS * sizeof(__half);   // 73728
    cudaFuncSetAttribute(cross_att_hmma10,
                         cudaFuncAttributeMaxDynamicSharedMemorySize, (int)smem_bytes);
    cudaFuncSetAttribute(cross_att_hmma10,
                         cudaFuncAttributePreferredSharedMemoryCarveout, 100);
    cross_att_hmma10<<<grid, 256, smem_bytes>>>(yhat, y, out);
}

// round 10
// speedup vs baseline: 1.1744x; 1.0764x over previous
#include <cuda_runtime.h>
#include <cuda_fp16.h>
#include <cstdint>

// CrossAttUnit fused — fp16-split (Ootomo) warp MMA, compact-smem 4-CTA/SM version.
// Fix vs R9: GEMM1 B-operand base address now includes the warp's ncol0 column
// block (logical granule bit 2), which was dropped and broke correctness.

#define HDIM 256
#define FPITCH 68

// dynamic smem byte offsets
#define AY_HI 0u
#define AY_LO 4096u
#define AH_HI 8192u
#define AH_LO 12288u
#define BST   16384u      // 4 x 4096: Khi,Klo,Qhi,Qlo (per chunk)
// GEMM2 tiles alias bytes 0..32768: ykhi 0, yklo 8192, yqhi 16384, yqlo 24576
#define LOGITS 32768u     // fp32 [64][68] = 17408 B
#define SMEM_BYTES 50176u

// pre-packed B image: [chunk 0..7][buf Khi,Klo,Qhi,Qlo][32 rows x 128 B, sw128]
__device__ __align__(16) unsigned char g_b[131072];

__global__ void split_kq_kernel(const float* __restrict__ kmat,
                                const float* __restrict__ qmat) {
    int gid = blockIdx.x * 256 + threadIdx.x;        // 32768 = 2 x 256 x 64
    int mat = gid >> 14, k = (gid >> 6) & 255, n = gid & 63;
    float x = mat ? qmat[k * 64 + n] : kmat[k * 64 + n];
    __half hi = __float2half_rn(x);
    __half lo = __float2half_rn(x - __half2float(hi));
    int c = k >> 5, kw = k & 31;
    uint32_t off = (uint32_t)(kw * 128 + (((n >> 3) ^ (kw & 7)) << 4) + (n & 7) * 2);
    uint32_t tb = (uint32_t)(c * 4 + mat * 2) * 4096u;
    *(__half*)&g_b[tb + off]         = hi;
    *(__half*)&g_b[tb + 4096u + off] = lo;
}

__device__ __forceinline__ uint32_t smem_u32(const void* p) {
    uint32_t a;
    asm("{ .reg .u64 t; cvta.to.shared.u64 t, %1; cvt.u32.u64 %0, t; }" : "=r"(a) : "l"(p));
    return a;
}
__device__ __forceinline__ void ldsm4(uint32_t r[4], uint32_t addr) {
    asm volatile("ldmatrix.sync.aligned.m8n8.x4.shared.b16 {%0,%1,%2,%3}, [%4];"
                 : "=r"(r[0]), "=r"(r[1]), "=r"(r[2]), "=r"(r[3]) : "r"(addr));
}
__device__ __forceinline__ void ldsm4t(uint32_t r[4], uint32_t addr) {
    asm volatile("ldmatrix.sync.aligned.m8n8.x4.trans.shared.b16 {%0,%1,%2,%3}, [%4];"
                 : "=r"(r[0]), "=r"(r[1]), "=r"(r[2]), "=r"(r[3]) : "r"(addr));
}
__device__ __forceinline__ void mma16816(float c[4], const uint32_t a[4],
                                         uint32_t b0, uint32_t b1) {
    asm("mma.sync.aligned.m16n8k16.row.col.f32.f16.f16.f32 "
        "{%0,%1,%2,%3},{%4,%5,%6,%7},{%8,%9},{%0,%1,%2,%3};"
        : "+f"(c[0]), "+f"(c[1]), "+f"(c[2]), "+f"(c[3])
        : "r"(a[0]), "r"(a[1]), "r"(a[2]), "r"(a[3]), "r"(b0), "r"(b1));
}
__device__ __forceinline__ void split2(float x0, float x1, uint32_t& hi, uint32_t& lo) {
    __half h0 = __float2half_rn(x0), h1 = __float2half_rn(x1);
    __half l0 = __float2half_rn(x0 - __half2float(h0));
    __half l1 = __float2half_rn(x1 - __half2float(h1));
    __half2 H = __halves2half2(h0, h1), L = __halves2half2(l0, l1);
    hi = *(uint32_t*)&H;
    lo = *(uint32_t*)&L;
}

#define CP_ASYNC16(saddr, gptr) \
    asm volatile("cp.async.cg.shared.global [%0], [%1], 16;" :: "r"(saddr), "l"(gptr) : "memory")
#define CP_COMMIT() asm volatile("cp.async.commit_group;" ::: "memory")
#define CP_WAIT0()  asm volatile("cp.async.wait_group 0;" ::: "memory")

__global__ __launch_bounds__(256, 4)
void cross_att_c4b(const float* __restrict__ yhat,
                   const float* __restrict__ y,
                   float* __restrict__ out) {
    extern __shared__ unsigned char smc[];
    const uint32_t sb = smem_u32(smc);
    const int tid = threadIdx.x, wid = tid >> 5, lane = tid & 31;
    __shared__ float part[4][64];
    __shared__ float csum_inv[64];

    const long rowbase = (long)blockIdx.x * 64;
    const int mat = wid >> 2;                // 0: yk (y,k) ; 1: yq (yhat,q)
    const int w2 = wid & 3;
    const int mrow0 = (w2 & 1) * 32;
    const int ncol0 = (w2 >> 1) * 32;

    float cc[2][4][4];
    #pragma unroll
    for (int a = 0; a < 2; a++)
        #pragma unroll
        for (int b = 0; b < 4; b++)
            #pragma unroll
            for (int j = 0; j < 4; j++) cc[a][b][j] = 0.0f;

    // ---- precomputed LDSM base addresses (constant across all 8 chunks) ----
    // A tiles: SW64, 64B rows. addr(row,g) = base + row*64 + ((g^((row>>1)&3))<<4)
    const uint32_t Abase = sb + (mat ? AH_HI : AY_HI);
    const int rowA0 = mrow0 + (lane & 15), rowA1 = rowA0 + 16;
    const int gA = lane >> 4;               // ks0 granule
    const uint32_t aH0 = Abase + (uint32_t)(rowA0 * 64 + ((gA ^ ((rowA0 >> 1) & 3)) << 4));
    const uint32_t aH1 = Abase + (uint32_t)(rowA1 * 64 + ((gA ^ ((rowA1 >> 1) & 3)) << 4));
    // ks1 variant: addr ^ 32 ; LO tile: addr + 4096
    // B tiles: SW128, 128B rows, trans. logical granule = (ncol0>>3) + nt*2 + gB
    const uint32_t Bbase = sb + BST + (mat ? 8192u : 0u);
    const int kB = ((lane >> 3) & 1) * 8 + (lane & 7);
    const int gB = ((lane >> 4) & 1) + (ncol0 >> 3);   // nt0, ks0 logical granule (bits disjoint)
    const uint32_t bH0 = Bbase + (uint32_t)(kB * 128 + ((gB ^ (kB & 7)) << 4));
    // nt1: ^32 ; ks1: +2048 ; LO: +4096

    // A staging source/dest (constant across chunks)
    const int sr = tid >> 3, sc4 = tid & 7;          // thread handles rows sr, sr+32
    const uint32_t soA = (uint32_t)(sr * 64 + (((sc4 >> 1) ^ ((sr >> 1) & 3)) << 4) + (sc4 & 1) * 8);
    const int sr2 = sr + 32;
    const uint32_t soA2 = (uint32_t)(sr2 * 64 + (((sc4 >> 1) ^ ((sr2 >> 1) & 3)) << 4) + (sc4 & 1) * 8);

    // ---------------- GEMM1: 8 chunks of K=32 ----------------
    #pragma unroll 1
    for (int c = 0; c < 8; c++) {
        // B: pre-swizzled image, 16 KB via cp.async
        {
            const char* src = (const char*)g_b + c * 16384;
            #pragma unroll
            for (int i = 0; i < 4; i++) {
                const uint32_t idx = (uint32_t)(i * 256 + tid);
                CP_ASYNC16(sb + BST + idx * 16u, src + idx * 16);
            }
            CP_COMMIT();
        }
        // A: 64 rows x 32 cols fp32 -> hi/lo fp16 (sw64 tiles)
        #pragma unroll
        for (int t = 0; t < 2; t++) {
            const int row = t ? sr2 : sr;
            const uint32_t so = t ? soA2 : soA;
            const long g = (rowbase + row) * HDIM + c * 32 + sc4 * 4;
            float4 vy = *(const float4*)&y[g];
            float4 vh = *(const float4*)&yhat[g];
            uint2 yh, yl, hh, hl;
            split2(vy.x, vy.y, yh.x, yl.x); split2(vy.z, vy.w, yh.y, yl.y);
            split2(vh.x, vh.y, hh.x, hl.x); split2(vh.z, vh.w, hh.y, hl.y);
            *(uint2*)(smc + AY_HI + so) = yh;
            *(uint2*)(smc + AY_LO + so) = yl;
            *(uint2*)(smc + AH_HI + so) = hh;
            *(uint2*)(smc + AH_LO + so) = hl;
        }
        CP_WAIT0();
        __syncthreads();

        #pragma unroll
        for (int ks = 0; ks < 2; ks++) {
            const uint32_t kx = ks ? 32u : 0u, dk = ks ? 2048u : 0u;
            uint32_t ah0[4], al0[4], ah1[4], al1[4];
            ldsm4(ah0, aH0 ^ kx);
            ldsm4(al0, (aH0 + 4096u) ^ kx);
            ldsm4(ah1, aH1 ^ kx);
            ldsm4(al1, (aH1 + 4096u) ^ kx);
            #pragma unroll
            for (int nt = 0; nt < 2; nt++) {
                const uint32_t nx = nt ? 32u : 0u;
                uint32_t bh[4], bl[4];
                ldsm4t(bh, (bH0 + dk) ^ nx);
                ldsm4t(bl, (bH0 + 4096u + dk) ^ nx);
                const int nb = 2 * nt;
                // per-accumulator order: hh, hl, lh (matches prior rounds)
                mma16816(cc[0][nb],     ah0, bh[0], bh[1]);
                mma16816(cc[0][nb + 1], ah0, bh[2], bh[3]);
                mma16816(cc[1][nb],     ah1, bh[0], bh[1]);
                mma16816(cc[1][nb + 1], ah1, bh[2], bh[3]);
                mma16816(cc[0][nb],     ah0, bl[0], bl[1]);
                mma16816(cc[0][nb + 1], ah0, bl[2], bl[3]);
                mma16816(cc[1][nb],     ah1, bl[0], bl[1]);
                mma16816(cc[1][nb + 1], ah1, bl[2], bl[3]);
                mma16816(cc[0][nb],     al0, bh[0], bh[1]);
                mma16816(cc[0][nb + 1], al0, bh[2], bh[3]);
                mma16816(cc[1][nb],     al1, bh[0], bh[1]);
                mma16816(cc[1][nb + 1], al1, bh[2], bh[3]);
            }
        }
        __syncthreads();
    }

    // ---------------- split yk/yq -> GEMM2 tiles (SW128, 64x128B) ----------------
    {
        const uint32_t HIb = mat ? 16384u : 0u;     // yq hi : yk hi
        const int rbase = mrow0 + (lane >> 2);
        const int cbase = ncol0 + (lane & 3) * 2;
        #pragma unroll
        for (int mt = 0; mt < 2; mt++) {
            #pragma unroll
            for (int nt = 0; nt < 4; nt++) {
                const int col = cbase + nt * 8;
                const uint32_t cpart = (uint32_t)(((col >> 3) << 4) + (col & 7) * 2);
                #pragma unroll
                for (int h = 0; h < 2; h++) {
                    const int r = rbase + mt * 16 + h * 8;
                    const uint32_t off = (uint32_t)(r * 128) + (cpart ^ (uint32_t)((r & 7) << 4));
                    uint32_t hi, lo;
                    split2(cc[mt][nt][2 * h], cc[mt][nt][2 * h + 1], hi, lo);
                    *(uint32_t*)(smc + HIb + off)         = hi;
                    *(uint32_t*)(smc + HIb + 8192u + off) = lo;
                }
            }
        }
    }
    __syncthreads();

    // ---------------- GEMM2: M = yk @ yq^T ; warp = (rt rows, ch col-half) ----------------
    float* attnf = (float*)(smc + LOGITS);          // [64][68] fp32, disjoint
    {
        const int rt = wid & 3, ch = wid >> 2;
        const int ct = ch * 32;
        float cm[4][4];
        #pragma unroll
        for (int n = 0; n < 4; n++)
            #pragma unroll
            for (int j = 0; j < 4; j++) cm[n][j] = 0.0f;

        const int rowG = rt * 16 + (lane & 15);
        const int g0 = lane >> 4;
        const uint32_t aBase = sb + (uint32_t)(rowG * 128 + ((g0 ^ (rowG & 7)) << 4));
        const int rowB0 = ct + (lane & 15), rowB1 = rowB0 + 16;
        const uint32_t bBase0 = sb + 16384u + (uint32_t)(rowB0 * 128 + ((g0 ^ (rowB0 & 7)) << 4));
        const uint32_t bBase1 = sb + 16384u + (uint32_t)(rowB1 * 128 + ((g0 ^ (rowB1 & 7)) << 4));

        #pragma unroll
        for (int ks = 0; ks < 4; ks++) {
            const uint32_t kx = (uint32_t)(ks * 32);      // XOR (granule bits)
            uint32_t Ah[4], Al[4];
            ldsm4(Ah, aBase ^ kx);
            ldsm4(Al, (aBase + 8192u) ^ kx);
            #pragma unroll
            for (int nl = 0; nl < 2; nl++) {
                const uint32_t bB = nl ? bBase1 : bBase0;
                uint32_t Bh[4], Bl[4];
                ldsm4(Bh, bB ^ kx);
                ldsm4(Bl, (bB + 8192u) ^ kx);
                const int nb = 2 * nl;
                mma16816(cm[nb],     Ah, Bh[0], Bh[2]);
                mma16816(cm[nb + 1], Ah, Bh[1], Bh[3]);
                mma16816(cm[nb],     Ah, Bl[0], Bl[2]);
                mma16816(cm[nb + 1], Ah, Bl[1], Bl[3]);
                mma16816(cm[nb],     Al, Bh[0], Bh[2]);
                mma16816(cm[nb + 1], Al, Bh[1], Bh[3]);
            }
        }
        // scaled logits -> disjoint region
        const int r0 = rt * 16 + (lane >> 2);
        const int cb = (lane & 3) * 2;
        #pragma unroll
        for (int nt = 0; nt < 4; nt++) {
            const int colb = ct + nt * 8 + cb;
            *(float2*)&attnf[r0 * FPITCH + colb] =
                make_float2(cm[nt][0] * 0.125f, cm[nt][1] * 0.125f);
            *(float2*)&attnf[(r0 + 8) * FPITCH + colb] =
                make_float2(cm[nt][2] * 0.125f, cm[nt][3] * 0.125f);
        }
    }
    __syncthreads();

    // ---------------- row softmax + EPS (8 warps x 8 rows) ----------------
    #pragma unroll 1
    for (int rr = 0; rr < 8; rr++) {
        const int r = wid * 8 + rr;
        float v0 = attnf[r * FPITCH + lane];
        float v1 = attnf[r * FPITCH + lane + 32];
        float mx = fmaxf(v0, v1);
        #pragma unroll
        for (int o = 16; o > 0; o >>= 1)
            mx = fmaxf(mx, __shfl_xor_sync(0xffffffffu, mx, o));
        float e0 = __expf(v0 - mx);
        float e1 = __expf(v1 - mx);
        float s = e0 + e1;
        #pragma unroll
        for (int o = 16; o > 0; o >>= 1)
            s += __shfl_xor_sync(0xffffffffu, s, o);
        const float inv = 1.0f / s;
        attnf[r * FPITCH + lane]      = e0 * inv + 1e-6f;
        attnf[r * FPITCH + lane + 32] = e1 * inv + 1e-6f;
    }
    __syncthreads();

    // ---------------- column sums + normalize + store ----------------
    {
        const int col = tid & 63, q = tid >> 6;
        float s = 0.0f;
        #pragma unroll
        for (int l = 0; l < 16; l++) s += attnf[(q * 16 + l) * FPITCH + col];
        part[q][col] = s;
    }
    __syncthreads();
    if (tid < 64)
        csum_inv[tid] = 1.0f / (part[0][tid] + part[1][tid] + part[2][tid] + part[3][tid]);
    __syncthreads();

    {
        float* outb = out + (long)blockIdx.x * 4096;
        #pragma unroll
        for (int e = 0; e < 4; e++) {
            const int f4 = e * 256 + tid;
            const int l = f4 >> 4, m0 = (f4 & 15) * 4;
            float4 v = *(const float4*)&attnf[l * FPITCH + m0];
            v.x *= csum_inv[m0 + 0];
            v.y *= csum_inv[m0 + 1];
            v.z *= csum_inv[m0 + 2];
            v.w *= csum_inv[m0 + 3];
            *(float4*)&outb[l * 64 + m0] = v;
        }
    }
}

extern "C" void kernel_launch(void* const* d_in, const int* in_sizes, int n_in,
                              void* d_out, int out_size) {
    const float* yhat = (const float*)d_in[0];
    const float* y    = (const float*)d_in[1];
    const float* kmat = (const float*)d_in[2];
    const float* qmat = (const float*)d_in[3];
    float* out = (float*)d_out;

    const int N = in_sizes[1] / HDIM;
    const int grid = N / 64;                 // 1 segment per CTA

    split_kq_kernel<<<128, 256>>>(kmat, qmat);

    cudaFuncSetAttribute(cross_att_c4b,
                         cudaFuncAttributeMaxDynamicSharedMemorySize, (int)SMEM_BYTES);
    cudaFuncSetAttribute(cross_att_c4b,
                         cudaFuncAttributePreferredSharedMemoryCarveout, 100);
    cross_att_c4b<<<grid, 256, SMEM_BYTES>>>(yhat, y, out);
}

// round 11
// speedup vs baseline: 1.1997x; 1.0216x over previous
#include <cuda_runtime.h>
#include <cuda_fp16.h>
#include <cstdint>

// CrossAttUnit fused — fp16-split (Ootomo) warp MMA, 4-CTA/SM, register epilogue.
// N=262144, H=256, D=64, L=64, B=4096. 1 segment/CTA, 256 threads.
// vs R10: softmax/colnorm done on GEMM2 register fragments (no logits smem).

#define HDIM 256

// dynamic smem byte offsets (32 KB total)
#define AY_HI 0u
#define AY_LO 4096u
#define AH_HI 8192u
#define AH_LO 12288u
#define BST   16384u      // 4 x 4096: Khi,Klo,Qhi,Qlo (per chunk)
// GEMM2 tiles alias bytes 0..32768: ykhi 0, yklo 8192, yqhi 16384, yqlo 24576
#define SMEM_BYTES 32768u

// pre-packed B image: [chunk 0..7][buf Khi,Klo,Qhi,Qlo][32 rows x 128 B, sw128]
__device__ __align__(16) unsigned char g_b[131072];

__global__ void split_kq_kernel(const float* __restrict__ kmat,
                                const float* __restrict__ qmat) {
    int gid = blockIdx.x * 256 + threadIdx.x;        // 32768 = 2 x 256 x 64
    int mat = gid >> 14, k = (gid >> 6) & 255, n = gid & 63;
    float x = mat ? qmat[k * 64 + n] : kmat[k * 64 + n];
    __half hi = __float2half_rn(x);
    __half lo = __float2half_rn(x - __half2float(hi));
    int c = k >> 5, kw = k & 31;
    uint32_t off = (uint32_t)(kw * 128 + (((n >> 3) ^ (kw & 7)) << 4) + (n & 7) * 2);
    uint32_t tb = (uint32_t)(c * 4 + mat * 2) * 4096u;
    *(__half*)&g_b[tb + off]         = hi;
    *(__half*)&g_b[tb + 4096u + off] = lo;
}

__device__ __forceinline__ uint32_t smem_u32(const void* p) {
    uint32_t a;
    asm("{ .reg .u64 t; cvta.to.shared.u64 t, %1; cvt.u32.u64 %0, t; }" : "=r"(a) : "l"(p));
    return a;
}
__device__ __forceinline__ void ldsm4(uint32_t r[4], uint32_t addr) {
    asm volatile("ldmatrix.sync.aligned.m8n8.x4.shared.b16 {%0,%1,%2,%3}, [%4];"
                 : "=r"(r[0]), "=r"(r[1]), "=r"(r[2]), "=r"(r[3]) : "r"(addr));
}
__device__ __forceinline__ void ldsm4t(uint32_t r[4], uint32_t addr) {
    asm volatile("ldmatrix.sync.aligned.m8n8.x4.trans.shared.b16 {%0,%1,%2,%3}, [%4];"
                 : "=r"(r[0]), "=r"(r[1]), "=r"(r[2]), "=r"(r[3]) : "r"(addr));
}
__device__ __forceinline__ void mma16816(float c[4], const uint32_t a[4],
                                         uint32_t b0, uint32_t b1) {
    asm("mma.sync.aligned.m16n8k16.row.col.f32.f16.f16.f32 "
        "{%0,%1,%2,%3},{%4,%5,%6,%7},{%8,%9},{%0,%1,%2,%3};"
        : "+f"(c[0]), "+f"(c[1]), "+f"(c[2]), "+f"(c[3])
        : "r"(a[0]), "r"(a[1]), "r"(a[2]), "r"(a[3]), "r"(b0), "r"(b1));
}
__device__ __forceinline__ void split2(float x0, float x1, uint32_t& hi, uint32_t& lo) {
    __half h0 = __float2half_rn(x0), h1 = __float2half_rn(x1);
    __half l0 = __float2half_rn(x0 - __half2float(h0));
    __half l1 = __float2half_rn(x1 - __half2float(h1));
    __half2 H = __halves2half2(h0, h1), L = __halves2half2(l0, l1);
    hi = *(uint32_t*)&H;
    lo = *(uint32_t*)&L;
}

#define CP_ASYNC16(saddr, gptr) \
    asm volatile("cp.async.cg.shared.global [%0], [%1], 16;" :: "r"(saddr), "l"(gptr) : "memory")
#define CP_COMMIT() asm volatile("cp.async.commit_group;" ::: "memory")
#define CP_WAIT0()  asm volatile("cp.async.wait_group 0;" ::: "memory")

__global__ __launch_bounds__(256, 4)
void cross_att_r11(const float* __restrict__ yhat,
                   const float* __restrict__ y,
                   float* __restrict__ out) {
    extern __shared__ unsigned char smc[];
    const uint32_t sb = smem_u32(smc);
    const int tid = threadIdx.x, wid = tid >> 5, lane = tid & 31;
    __shared__ float rred[2][64];      // row-max exchange [ch][row]
    __shared__ float rsum[2][64];      // row-sum exchange
    __shared__ float cpart[4][64];     // column partial sums [rt][col]
    __shared__ float csum_inv[64];

    const long rowbase = (long)blockIdx.x * 64;
    const int mat = wid >> 2;                // 0: yk (y,k) ; 1: yq (yhat,q)
    const int w2 = wid & 3;
    const int mrow0 = (w2 & 1) * 32;
    const int ncol0 = (w2 >> 1) * 32;

    float cc[2][4][4];
    #pragma unroll
    for (int a = 0; a < 2; a++)
        #pragma unroll
        for (int b = 0; b < 4; b++)
            #pragma unroll
            for (int j = 0; j < 4; j++) cc[a][b][j] = 0.0f;

    // ---- precomputed LDSM base addresses (constant across all 8 chunks) ----
    const uint32_t Abase = sb + (mat ? AH_HI : AY_HI);
    const int rowA0 = mrow0 + (lane & 15), rowA1 = rowA0 + 16;
    const int gA = lane >> 4;
    const uint32_t aH0 = Abase + (uint32_t)(rowA0 * 64 + ((gA ^ ((rowA0 >> 1) & 3)) << 4));
    const uint32_t aH1 = Abase + (uint32_t)(rowA1 * 64 + ((gA ^ ((rowA1 >> 1) & 3)) << 4));
    const uint32_t Bbase = sb + BST + (mat ? 8192u : 0u);
    const int kB = ((lane >> 3) & 1) * 8 + (lane & 7);
    const int gB = ((lane >> 4) & 1) + (ncol0 >> 3);   // logical granule incl. warp col block
    const uint32_t bH0 = Bbase + (uint32_t)(kB * 128 + ((gB ^ (kB & 7)) << 4));

    // A staging source/dest (constant across chunks)
    const int sr = tid >> 3, sc4 = tid & 7;
    const uint32_t soA = (uint32_t)(sr * 64 + (((sc4 >> 1) ^ ((sr >> 1) & 3)) << 4) + (sc4 & 1) * 8);
    const int sr2 = sr + 32;
    const uint32_t soA2 = (uint32_t)(sr2 * 64 + (((sc4 >> 1) ^ ((sr2 >> 1) & 3)) << 4) + (sc4 & 1) * 8);

    // ---------------- GEMM1: 8 chunks of K=32 ----------------
    #pragma unroll 1
    for (int c = 0; c < 8; c++) {
        {
            const char* src = (const char*)g_b + c * 16384;
            #pragma unroll
            for (int i = 0; i < 4; i++) {
                const uint32_t idx = (uint32_t)(i * 256 + tid);
                CP_ASYNC16(sb + BST + idx * 16u, src + idx * 16);
            }
            CP_COMMIT();
        }
        #pragma unroll
        for (int t = 0; t < 2; t++) {
            const int row = t ? sr2 : sr;
            const uint32_t so = t ? soA2 : soA;
            const long g = (rowbase + row) * HDIM + c * 32 + sc4 * 4;
            float4 vy = *(const float4*)&y[g];
            float4 vh = *(const float4*)&yhat[g];
            uint2 yh, yl, hh, hl;
            split2(vy.x, vy.y, yh.x, yl.x); split2(vy.z, vy.w, yh.y, yl.y);
            split2(vh.x, vh.y, hh.x, hl.x); split2(vh.z, vh.w, hh.y, hl.y);
            *(uint2*)(smc + AY_HI + so) = yh;
            *(uint2*)(smc + AY_LO + so) = yl;
            *(uint2*)(smc + AH_HI + so) = hh;
            *(uint2*)(smc + AH_LO + so) = hl;
        }
        CP_WAIT0();
        __syncthreads();

        #pragma unroll
        for (int ks = 0; ks < 2; ks++) {
            const uint32_t kx = ks ? 32u : 0u, dk = ks ? 2048u : 0u;
            uint32_t ah0[4], al0[4], ah1[4], al1[4];
            ldsm4(ah0, aH0 ^ kx);
            ldsm4(al0, (aH0 + 4096u) ^ kx);
            ldsm4(ah1, aH1 ^ kx);
            ldsm4(al1, (aH1 + 4096u) ^ kx);
            #pragma unroll
            for (int nt = 0; nt < 2; nt++) {
                const uint32_t nx = nt ? 32u : 0u;
                uint32_t bh[4], bl[4];
                ldsm4t(bh, (bH0 + dk) ^ nx);
                ldsm4t(bl, (bH0 + 4096u + dk) ^ nx);
                const int nb = 2 * nt;
                mma16816(cc[0][nb],     ah0, bh[0], bh[1]);
                mma16816(cc[0][nb + 1], ah0, bh[2], bh[3]);
                mma16816(cc[1][nb],     ah1, bh[0], bh[1]);
                mma16816(cc[1][nb + 1], ah1, bh[2], bh[3]);
                mma16816(cc[0][nb],     ah0, bl[0], bl[1]);
                mma16816(cc[0][nb + 1], ah0, bl[2], bl[3]);
                mma16816(cc[1][nb],     ah1, bl[0], bl[1]);
                mma16816(cc[1][nb + 1], ah1, bl[2], bl[3]);
                mma16816(cc[0][nb],     al0, bh[0], bh[1]);
                mma16816(cc[0][nb + 1], al0, bh[2], bh[3]);
                mma16816(cc[1][nb],     al1, bh[0], bh[1]);
                mma16816(cc[1][nb + 1], al1, bh[2], bh[3]);
            }
        }
        __syncthreads();
    }

    // ---------------- split yk/yq -> GEMM2 tiles (SW128, 64x128B) ----------------
    {
        const uint32_t HIb = mat ? 16384u : 0u;
        const int rbase = mrow0 + (lane >> 2);
        const int cbase = ncol0 + (lane & 3) * 2;
        #pragma unroll
        for (int mt = 0; mt < 2; mt++) {
            #pragma unroll
            for (int nt = 0; nt < 4; nt++) {
                const int col = cbase + nt * 8;
                const uint32_t cpartb = (uint32_t)(((col >> 3) << 4) + (col & 7) * 2);
                #pragma unroll
                for (int h = 0; h < 2; h++) {
                    const int r = rbase + mt * 16 + h * 8;
                    const uint32_t off = (uint32_t)(r * 128) + (cpartb ^ (uint32_t)((r & 7) << 4));
                    uint32_t hi, lo;
                    split2(cc[mt][nt][2 * h], cc[mt][nt][2 * h + 1], hi, lo);
                    *(uint32_t*)(smc + HIb + off)         = hi;
                    *(uint32_t*)(smc + HIb + 8192u + off) = lo;
                }
            }
        }
    }
    __syncthreads();

    // ---------------- GEMM2 + register epilogue ----------------
    {
        const int rt = wid & 3, ch = wid >> 2;
        const int ct = ch * 32;
        float cm[4][4];
        #pragma unroll
        for (int n = 0; n < 4; n++)
            #pragma unroll
            for (int j = 0; j < 4; j++) cm[n][j] = 0.0f;

        const int rowG = rt * 16 + (lane & 15);
        const int g0 = lane >> 4;
        const uint32_t aBase = sb + (uint32_t)(rowG * 128 + ((g0 ^ (rowG & 7)) << 4));
        const int rowB0 = ct + (lane & 15), rowB1 = rowB0 + 16;
        const uint32_t bBase0 = sb + 16384u + (uint32_t)(rowB0 * 128 + ((g0 ^ (rowB0 & 7)) << 4));
        const uint32_t bBase1 = sb + 16384u + (uint32_t)(rowB1 * 128 + ((g0 ^ (rowB1 & 7)) << 4));

        #pragma unroll
        for (int ks = 0; ks < 4; ks++) {
            const uint32_t kx = (uint32_t)(ks * 32);
            uint32_t Ah[4], Al[4];
            ldsm4(Ah, aBase ^ kx);
            ldsm4(Al, (aBase + 8192u) ^ kx);
            #pragma unroll
            for (int nl = 0; nl < 2; nl++) {
                const uint32_t bB = nl ? bBase1 : bBase0;
                uint32_t Bh[4], Bl[4];
                ldsm4(Bh, bB ^ kx);
                ldsm4(Bl, (bB + 8192u) ^ kx);
                const int nb = 2 * nl;
                mma16816(cm[nb],     Ah, Bh[0], Bh[2]);
                mma16816(cm[nb + 1], Ah, Bh[1], Bh[3]);
                mma16816(cm[nb],     Ah, Bl[0], Bl[2]);
                mma16816(cm[nb + 1], Ah, Bl[1], Bl[3]);
                mma16816(cm[nb],     Al, Bh[0], Bh[2]);
                mma16816(cm[nb + 1], Al, Bh[1], Bh[3]);
            }
        }

        // ---- scale ----
        #pragma unroll
        for (int nt = 0; nt < 4; nt++)
            #pragma unroll
            for (int j = 0; j < 4; j++) cm[nt][j] *= 0.125f;

        const int r0 = rt * 16 + (lane >> 2);
        const int cb = (lane & 3) * 2;

        // ---- row max (rows r0, r0+8) over warp's 32 cols, then cross-warp ----
        float m0 = fmaxf(fmaxf(cm[0][0], cm[0][1]), fmaxf(cm[1][0], cm[1][1]));
        m0 = fmaxf(m0, fmaxf(fmaxf(cm[2][0], cm[2][1]), fmaxf(cm[3][0], cm[3][1])));
        float m1 = fmaxf(fmaxf(cm[0][2], cm[0][3]), fmaxf(cm[1][2], cm[1][3]));
        m1 = fmaxf(m1, fmaxf(fmaxf(cm[2][2], cm[2][3]), fmaxf(cm[3][2], cm[3][3])));
        m0 = fmaxf(m0, __shfl_xor_sync(0xffffffffu, m0, 1));
        m0 = fmaxf(m0, __shfl_xor_sync(0xffffffffu, m0, 2));
        m1 = fmaxf(m1, __shfl_xor_sync(0xffffffffu, m1, 1));
        m1 = fmaxf(m1, __shfl_xor_sync(0xffffffffu, m1, 2));
        if ((lane & 3) == 0) { rred[ch][r0] = m0; rred[ch][r0 + 8] = m1; }
        __syncthreads();
        m0 = fmaxf(m0, rred[ch ^ 1][r0]);
        m1 = fmaxf(m1, rred[ch ^ 1][r0 + 8]);

        // ---- exp + row sums ----
        float s0 = 0.0f, s1 = 0.0f;
        #pragma unroll
        for (int nt = 0; nt < 4; nt++) {
            cm[nt][0] = __expf(cm[nt][0] - m0); s0 += cm[nt][0];
            cm[nt][1] = __expf(cm[nt][1] - m0); s0 += cm[nt][1];
            cm[nt][2] = __expf(cm[nt][2] - m1); s1 += cm[nt][2];
            cm[nt][3] = __expf(cm[nt][3] - m1); s1 += cm[nt][3];
        }
        s0 += __shfl_xor_sync(0xffffffffu, s0, 1);
        s0 += __shfl_xor_sync(0xffffffffu, s0, 2);
        s1 += __shfl_xor_sync(0xffffffffu, s1, 1);
        s1 += __shfl_xor_sync(0xffffffffu, s1, 2);
        if ((lane & 3) == 0) { rsum[ch][r0] = s0; rsum[ch][r0 + 8] = s1; }
        __syncthreads();
        s0 += rsum[ch ^ 1][r0];
        s1 += rsum[ch ^ 1][r0 + 8];
        const float inv0 = 1.0f / s0, inv1 = 1.0f / s1;
        #pragma unroll
        for (int nt = 0; nt < 4; nt++) {
            cm[nt][0] = cm[nt][0] * inv0 + 1e-6f;
            cm[nt][1] = cm[nt][1] * inv0 + 1e-6f;
            cm[nt][2] = cm[nt][2] * inv1 + 1e-6f;
            cm[nt][3] = cm[nt][3] * inv1 + 1e-6f;
        }

        // ---- column partial sums (warp's 16 rows) ----
        float cs0[4], cs1[4];
        #pragma unroll
        for (int nt = 0; nt < 4; nt++) {
            cs0[nt] = cm[nt][0] + cm[nt][2];
            cs1[nt] = cm[nt][1] + cm[nt][3];
        }
        #pragma unroll
        for (int o = 4; o < 32; o <<= 1) {
            #pragma unroll
            for (int nt = 0; nt < 4; nt++) {
                cs0[nt] += __shfl_xor_sync(0xffffffffu, cs0[nt], o);
                cs1[nt] += __shfl_xor_sync(0xffffffffu, cs1[nt], o);
            }
        }
        if ((lane >> 2) == 0) {
            #pragma unroll
            for (int nt = 0; nt < 4; nt++) {
                const int col = ct + nt * 8 + cb;
                cpart[rt][col]     = cs0[nt];
                cpart[rt][col + 1] = cs1[nt];
            }
        }
        __syncthreads();
        if (tid < 64)
            csum_inv[tid] = 1.0f / (cpart[0][tid] + cpart[1][tid] + cpart[2][tid] + cpart[3][tid]);
        __syncthreads();

        // ---- normalize + store straight from registers ----
        float* outb = out + (long)blockIdx.x * 4096;
        #pragma unroll
        for (int nt = 0; nt < 4; nt++) {
            const int col = ct + nt * 8 + cb;
            const float i0 = csum_inv[col], i1 = csum_inv[col + 1];
            *(float2*)&outb[r0 * 64 + col] =
                make_float2(cm[nt][0] * i0, cm[nt][1] * i1);
            *(float2*)&outb[(r0 + 8) * 64 + col] =
                make_float2(cm[nt][2] * i0, cm[nt][3] * i1);
        }
    }
}

extern "C" void kernel_launch(void* const* d_in, const int* in_sizes, int n_in,
                              void* d_out, int out_size) {
    const float* yhat = (const float*)d_in[0];
    const float* y    = (const float*)d_in[1];
    const float* kmat = (const float*)d_in[2];
    const float* qmat = (const float*)d_in[3];
    float* out = (float*)d_out;

    const int N = in_sizes[1] / HDIM;
    const int grid = N / 64;                 // 1 segment per CTA

    split_kq_kernel<<<128, 256>>>(kmat, qmat);

    cudaFuncSetAttribute(cross_att_r11,
                         cudaFuncAttributeMaxDynamicSharedMemorySize, (int)SMEM_BYTES);
    cudaFuncSetAttribute(cross_att_r11,
                         cudaFuncAttributePreferredSharedMemoryCarveout, 100);
    cross_att_r11<<<grid, 256, SMEM_BYTES>>>(yhat, y, out);
}